// round 5
// baseline (speedup 1.0000x reference)
#include <cuda_runtime.h>
#include <cstddef>

// Problem constants
namespace {
constexpr int kB  = 2;
constexpr int kN  = 2048;
constexpr int kD  = 1024;
constexpr int kH  = 16;
constexpr int kDH = 64;          // head dim
constexpr int kM  = kB * kN;     // 4096 flattened rows
constexpr int kE  = 3 * kDH;     // 192 (k,q,v per head)
}

// Scratch (device globals; no runtime allocation allowed)
__device__ float g_q[kB * kH * kN * kDH];
__device__ float g_k[kB * kH * kN * kDH];
__device__ float g_v[kB * kH * kN * kDH];
__device__ float g_sa[kB * kN * kD];

// ---------------------------------------------------------------------------
// Kernel 1: per-head KQV projection.
//   kqv[b,h,n,e] = sum_d x[b,n,d] * W_kqv[h,d,e] + b_kqv[h,e]
// grid: (M/64, 3, H); blockIdx.y selects the 64-wide e-chunk = k / q / v.
// 64x64x16 tile, 256 threads, 4x4 micro-tile per thread.
// ---------------------------------------------------------------------------
__global__ __launch_bounds__(256) void kqv_kernel(const float* __restrict__ x,
                                                  const float* __restrict__ W,
                                                  const float* __restrict__ bias) {
    const int h  = blockIdx.z;
    const int e0 = blockIdx.y * 64;       // 0 (k), 64 (q), 128 (v)
    const int m0 = blockIdx.x * 64;

    __shared__ float As[16][64];          // As[k][m]
    __shared__ float Bs[16][64];          // Bs[k][n]

    const int tid = threadIdx.x;
    const int ty = tid / 16, tx = tid % 16;

    const float* Wh = W + (size_t)h * kD * kE;

    float acc[4][4] = {};

    for (int k0 = 0; k0 < kD; k0 += 16) {
        {   // load A tile 64x16 (coalesced over k)
            const int kk = tid % 16, mm = tid / 16;
            #pragma unroll
            for (int i = 0; i < 4; i++)
                As[kk][mm + i * 16] = x[(size_t)(m0 + mm + i * 16) * kD + k0 + kk];
        }
        {   // load B tile 16x64 (coalesced over n)
            const int nn = tid % 64, kk = tid / 64;
            #pragma unroll
            for (int i = 0; i < 4; i++)
                Bs[kk + i * 4][nn] = Wh[(size_t)(k0 + kk + i * 4) * kE + e0 + nn];
        }
        __syncthreads();
        #pragma unroll
        for (int k = 0; k < 16; k++) {
            const float4 a4 = *reinterpret_cast<const float4*>(&As[k][ty * 4]);
            const float4 b4 = *reinterpret_cast<const float4*>(&Bs[k][tx * 4]);
            const float a[4] = {a4.x, a4.y, a4.z, a4.w};
            const float b[4] = {b4.x, b4.y, b4.z, b4.w};
            #pragma unroll
            for (int i = 0; i < 4; i++)
                #pragma unroll
                for (int j = 0; j < 4; j++)
                    acc[i][j] += a[i] * b[j];
        }
        __syncthreads();
    }

    // chunk order in reference is k, q, v
    float* dst = (blockIdx.y == 0) ? g_k : (blockIdx.y == 1 ? g_q : g_v);

    #pragma unroll
    for (int i = 0; i < 4; i++) {
        const int m  = m0 + ty * 4 + i;
        const int b_ = m / kN, n = m % kN;
        #pragma unroll
        for (int j = 0; j < 4; j++) {
            const int col = tx * 4 + j;
            const float v = acc[i][j] + bias[h * kE + e0 + col];
            dst[((size_t)(b_ * kH + h) * kN + n) * kDH + col] = v;
        }
    }
}

// ---------------------------------------------------------------------------
// Kernel 2: causal flash attention per (b,h).
// grid: (N/64, B*H); block: 64 threads, one thread per query row.
// Q row + O accumulator + scores live in registers; K/V tiles (32 keys) in smem,
// read as broadcast float4. Online softmax (running max / sum).
// ---------------------------------------------------------------------------
__global__ __launch_bounds__(64) void attn_kernel() {
    const int qt = blockIdx.x;
    const int bh = blockIdx.y;
    const int r  = threadIdx.x;
    const int qi = qt * 64 + r;

    const float* qb = g_q + (size_t)bh * kN * kDH;
    const float* kb = g_k + (size_t)bh * kN * kDH;
    const float* vb = g_v + (size_t)bh * kN * kDH;

    __shared__ float Ks[32][64];
    __shared__ float Vs[32][64];

    // Q row in registers, pre-scaled by 1/sqrt(DH) = 0.125
    float4 q4[16];
    {
        const float4* qr = reinterpret_cast<const float4*>(qb + (size_t)qi * kDH);
        #pragma unroll
        for (int i = 0; i < 16; i++) {
            float4 t = qr[i];
            t.x *= 0.125f; t.y *= 0.125f; t.z *= 0.125f; t.w *= 0.125f;
            q4[i] = t;
        }
    }

    float O[64];
    #pragma unroll
    for (int d = 0; d < 64; d++) O[d] = 0.f;
    float mrun = -1e30f, lrun = 0.f;

    const int ktiles = 2 * qt + 2;   // 32-key tiles covering keys [0, qt*64+63]
    for (int kt = 0; kt < ktiles; kt++) {
        __syncthreads();
        #pragma unroll
        for (int j = 0; j < 32; j++) {
            const size_t krow = (size_t)(kt * 32 + j) * kDH + r;
            Ks[j][r] = kb[krow];
            Vs[j][r] = vb[krow];
        }
        __syncthreads();

        const int climit = qi - kt * 32 + 1;   // #valid key columns in this tile

        float s[32];
        #pragma unroll
        for (int c = 0; c < 32; c++) {
            const float4* krow4 = reinterpret_cast<const float4*>(&Ks[c][0]);
            float acc = 0.f;
            #pragma unroll
            for (int d4 = 0; d4 < 16; d4++) {
                const float4 kv = krow4[d4];
                const float4 qv = q4[d4];
                acc += qv.x * kv.x;
                acc += qv.y * kv.y;
                acc += qv.z * kv.z;
                acc += qv.w * kv.w;
            }
            s[c] = (c < climit) ? acc : -1e30f;
        }

        float tmax = -1e30f;
        #pragma unroll
        for (int c = 0; c < 32; c++) tmax = fmaxf(tmax, s[c]);

        const float mnew  = fmaxf(mrun, tmax);
        const float alpha = __expf(mrun - mnew);
        float rowsum = 0.f;
        #pragma unroll
        for (int c = 0; c < 32; c++) {
            const float p = __expf(s[c] - mnew);
            s[c] = p;
            rowsum += p;
        }
        lrun = lrun * alpha + rowsum;
        mrun = mnew;

        #pragma unroll
        for (int d = 0; d < 64; d++) O[d] *= alpha;

        #pragma unroll
        for (int c = 0; c < 32; c++) {
            const float pc = s[c];
            const float4* vrow4 = reinterpret_cast<const float4*>(&Vs[c][0]);
            #pragma unroll
            for (int d4 = 0; d4 < 16; d4++) {
                const float4 vv = vrow4[d4];
                O[4 * d4 + 0] += pc * vv.x;
                O[4 * d4 + 1] += pc * vv.y;
                O[4 * d4 + 2] += pc * vv.z;
                O[4 * d4 + 3] += pc * vv.w;
            }
        }
    }

    const float inv = 1.f / lrun;
    const int b_ = bh / kH, h = bh % kH;
    float* dst = g_sa + ((size_t)(b_ * kN + qi)) * kD + h * kDH;   // head-concat layout
    #pragma unroll
    for (int d4 = 0; d4 < 16; d4++) {
        float4 o;
        o.x = O[4 * d4 + 0] * inv;
        o.y = O[4 * d4 + 1] * inv;
        o.z = O[4 * d4 + 2] * inv;
        o.w = O[4 * d4 + 3] * inv;
        reinterpret_cast<float4*>(dst)[d4] = o;
    }
}

// ---------------------------------------------------------------------------
// Kernel 3: output projection. out = sa @ W_proj^T + b_proj  (NT GEMM)
// grid: (M/64, D/64); 64x64x16 tile, 256 threads, 4x4 micro-tile.
// ---------------------------------------------------------------------------
__global__ __launch_bounds__(256) void proj_kernel(const float* __restrict__ Wp,
                                                   const float* __restrict__ bp,
                                                   float* __restrict__ out) {
    const int m0 = blockIdx.x * 64, n0 = blockIdx.y * 64;

    __shared__ float As[16][64];   // As[k][m]
    __shared__ float Bs[16][64];   // Bs[k][n]  (= W_proj[n][k])

    const int tid = threadIdx.x;
    const int ty = tid / 16, tx = tid % 16;

    float acc[4][4] = {};

    for (int k0 = 0; k0 < kD; k0 += 16) {
        {
            const int kk = tid % 16, mm = tid / 16;
            #pragma unroll
            for (int i = 0; i < 4; i++)
                As[kk][mm + i * 16] = g_sa[(size_t)(m0 + mm + i * 16) * kD + k0 + kk];
        }
        {
            const int kk = tid % 16, nn = tid / 16;
            #pragma unroll
            for (int i = 0; i < 4; i++)
                Bs[kk][nn + i * 16] = Wp[(size_t)(n0 + nn + i * 16) * kD + k0 + kk];
        }
        __syncthreads();
        #pragma unroll
        for (int k = 0; k < 16; k++) {
            const float4 a4 = *reinterpret_cast<const float4*>(&As[k][ty * 4]);
            const float4 b4 = *reinterpret_cast<const float4*>(&Bs[k][tx * 4]);
            const float a[4] = {a4.x, a4.y, a4.z, a4.w};
            const float b[4] = {b4.x, b4.y, b4.z, b4.w};
            #pragma unroll
            for (int i = 0; i < 4; i++)
                #pragma unroll
                for (int j = 0; j < 4; j++)
                    acc[i][j] += a[i] * b[j];
        }
        __syncthreads();
    }

    #pragma unroll
    for (int i = 0; i < 4; i++) {
        const int m = m0 + ty * 4 + i;
        #pragma unroll
        for (int j = 0; j < 4; j++) {
            const int n = n0 + tx * 4 + j;
            out[(size_t)m * kD + n] = acc[i][j] + bp[n];
        }
    }
}

// ---------------------------------------------------------------------------
extern "C" void kernel_launch(void* const* d_in, const int* in_sizes, int n_in,
                              void* d_out, int out_size) {
    (void)in_sizes; (void)n_in; (void)out_size;
    const float* x      = (const float*)d_in[0];
    const float* W_kqv  = (const float*)d_in[1];
    const float* b_kqv  = (const float*)d_in[2];
    const float* W_proj = (const float*)d_in[3];
    const float* b_proj = (const float*)d_in[4];
    float* out = (float*)d_out;

    dim3 gA(kM / 64, 3, kH);
    kqv_kernel<<<gA, 256>>>(x, W_kqv, b_kqv);

    dim3 gB(kN / 64, kB * kH);
    attn_kernel<<<gB, 64>>>();

    dim3 gC(kM / 64, kD / 64);
    proj_kernel<<<gC, 256>>>(W_proj, b_proj, out);
}

// round 8
// speedup vs baseline: 1.4500x; 1.4500x over previous
#include <cuda_runtime.h>
#include <cstddef>

// Problem constants
namespace {
constexpr int kB  = 2;
constexpr int kN  = 2048;
constexpr int kD  = 1024;
constexpr int kH  = 16;
constexpr int kDH = 64;              // head dim
constexpr int kM  = kB * kN;         // 4096 flattened rows
constexpr int kE  = 3 * kDH;         // 192 per head
constexpr int kEtot = kH * kE;       // 3072 fused kqv columns
}

// Scratch (device globals; no runtime allocation allowed)
__device__ float g_q[kB * kH * kN * kDH];
__device__ float g_k[kB * kH * kN * kDH];
__device__ float g_v[kB * kH * kN * kDH];
__device__ float g_sa[kB * kN * kD];

// ---------------------------------------------------------------------------
// Packed fp32x2 helpers (sm_103a FFMA2 path — only reachable via PTX)
// ---------------------------------------------------------------------------
__device__ __forceinline__ unsigned long long ffma2(unsigned long long a,
                                                    unsigned long long b,
                                                    unsigned long long c) {
    unsigned long long d;
    asm("fma.rn.f32x2 %0, %1, %2, %3;" : "=l"(d) : "l"(a), "l"(b), "l"(c));
    return d;
}
__device__ __forceinline__ unsigned long long fmul2(unsigned long long a,
                                                    unsigned long long b) {
    unsigned long long d;
    asm("mul.rn.f32x2 %0, %1, %2;" : "=l"(d) : "l"(a), "l"(b));
    return d;
}
__device__ __forceinline__ unsigned long long fadd2(unsigned long long a,
                                                    unsigned long long b) {
    unsigned long long d;
    asm("add.rn.f32x2 %0, %1, %2;" : "=l"(d) : "l"(a), "l"(b));
    return d;
}
__device__ __forceinline__ unsigned long long dup2(float a) {
    unsigned long long r;
    unsigned int u = __float_as_uint(a);
    asm("mov.b64 %0, {%1, %1};" : "=l"(r) : "r"(u));
    return r;
}
__device__ __forceinline__ float2 unpack2(unsigned long long v) {
    float2 r;
    asm("mov.b64 {%0, %1}, %2;" : "=f"(r.x), "=f"(r.y) : "l"(v));
    return r;
}

// ---------------------------------------------------------------------------
// Kernel 1: fused KQV projection as ONE GEMM.
//   out[m, j] = sum_d x[m,d] * W_kqv[h, d, r] + b_kqv[h, r],  j = h*192 + r
// 128x128x16 tile, 256 threads, 8x8 micro-tile, f32x2 FMA.
// ---------------------------------------------------------------------------
__global__ __launch_bounds__(256) void kqv_kernel(const float* __restrict__ x,
                                                  const float* __restrict__ W,
                                                  const float* __restrict__ bias) {
    const int m0 = blockIdx.x * 128;
    const int n0 = blockIdx.y * 128;

    __shared__ __align__(16) float As[16][132];   // As[k][m] (padded)
    __shared__ __align__(16) float Bs[16][132];   // Bs[k][n] (padded)

    const int tid = threadIdx.x;
    const int ty = tid / 16, tx = tid % 16;

    unsigned long long acc[8][4];
    #pragma unroll
    for (int i = 0; i < 8; i++)
        #pragma unroll
        for (int j = 0; j < 4; j++) acc[i][j] = 0ULL;

    for (int k0 = 0; k0 < kD; k0 += 16) {
        // A tile 128(m) x 16(k): float4 reads along k
        #pragma unroll
        for (int it = 0; it < 2; it++) {
            const int fi = tid + it * 256;           // 0..511
            const int mm = fi >> 2, kq = fi & 3;
            const float4 v = *reinterpret_cast<const float4*>(
                &x[(size_t)(m0 + mm) * kD + k0 + kq * 4]);
            As[kq * 4 + 0][mm] = v.x;
            As[kq * 4 + 1][mm] = v.y;
            As[kq * 4 + 2][mm] = v.z;
            As[kq * 4 + 3][mm] = v.w;
        }
        // B tile 16(k) x 128(n): scalar, coalesced along n (within head segs)
        #pragma unroll
        for (int it = 0; it < 8; it++) {
            const int idx = tid + it * 256;          // 0..2047
            const int kk = idx >> 7, nn = idx & 127;
            const int j = n0 + nn;
            const int h = j / kE, r = j % kE;
            Bs[kk][nn] = W[(size_t)h * kD * kE + (size_t)(k0 + kk) * kE + r];
        }
        __syncthreads();

        #pragma unroll
        for (int k = 0; k < 16; k++) {
            const float4* apf = reinterpret_cast<const float4*>(&As[k][ty * 8]);
            const float4 a0 = apf[0], a1 = apf[1];
            unsigned long long ad[8];
            ad[0] = dup2(a0.x); ad[1] = dup2(a0.y);
            ad[2] = dup2(a0.z); ad[3] = dup2(a0.w);
            ad[4] = dup2(a1.x); ad[5] = dup2(a1.y);
            ad[6] = dup2(a1.z); ad[7] = dup2(a1.w);

            const ulonglong2* bp = reinterpret_cast<const ulonglong2*>(&Bs[k][tx * 8]);
            const ulonglong2 b01 = bp[0], b23 = bp[1];
            const unsigned long long b2[4] = {b01.x, b01.y, b23.x, b23.y};

            #pragma unroll
            for (int i = 0; i < 8; i++)
                #pragma unroll
                for (int j = 0; j < 4; j++)
                    acc[i][j] = ffma2(ad[i], b2[j], acc[i][j]);
        }
        __syncthreads();
    }

    // Epilogue. Thread's 8 columns lie in one head & one chunk (8 | 64).
    const int jbase = n0 + tx * 8;
    const int h = jbase / kE, r = jbase % kE;
    const int chunk = r / kDH, e = r % kDH;
    float* dst = (chunk == 0) ? g_k : (chunk == 1 ? g_q : g_v);

    float b8[8];
    #pragma unroll
    for (int jj = 0; jj < 8; jj++) b8[jj] = bias[h * kE + r + jj];

    #pragma unroll
    for (int i = 0; i < 8; i++) {
        const int m = m0 + ty * 8 + i;
        const int b_ = m >> 11, n = m & (kN - 1);
        float o[8];
        #pragma unroll
        for (int j2 = 0; j2 < 4; j2++) {
            const float2 p = unpack2(acc[i][j2]);
            o[2 * j2 + 0] = p.x + b8[2 * j2 + 0];
            o[2 * j2 + 1] = p.y + b8[2 * j2 + 1];
        }
        float* d = dst + ((size_t)(b_ * kH + h) * kN + n) * kDH + e;
        *reinterpret_cast<float4*>(d + 0) = make_float4(o[0], o[1], o[2], o[3]);
        *reinterpret_cast<float4*>(d + 4) = make_float4(o[4], o[5], o[6], o[7]);
    }
}

// ---------------------------------------------------------------------------
// Kernel 2: causal flash attention per (b,h), f32x2 inner loops.
// grid: (N/64, B*H); block 64 threads, one thread per query row.
// ---------------------------------------------------------------------------
__global__ __launch_bounds__(64) void attn_kernel() {
    const int qt = gridDim.x - 1 - blockIdx.x;   // heavy blocks first
    const int bh = blockIdx.y;
    const int r  = threadIdx.x;
    const int qi = qt * 64 + r;

    const float* qb = g_q + (size_t)bh * kN * kDH;
    const float* kb = g_k + (size_t)bh * kN * kDH;
    const float* vb = g_v + (size_t)bh * kN * kDH;

    __shared__ __align__(16) float Ks[32][64];
    __shared__ __align__(16) float Vs[32][64];

    // Q row as 32 packed pairs, pre-scaled by 1/sqrt(DH)=0.125
    unsigned long long q2[32];
    {
        const ulonglong2* qr = reinterpret_cast<const ulonglong2*>(qb + (size_t)qi * kDH);
        const unsigned long long sc = dup2(0.125f);
        #pragma unroll
        for (int i = 0; i < 16; i++) {
            const ulonglong2 t = qr[i];
            q2[2 * i + 0] = fmul2(t.x, sc);
            q2[2 * i + 1] = fmul2(t.y, sc);
        }
    }

    unsigned long long O2[32];
    #pragma unroll
    for (int i = 0; i < 32; i++) O2[i] = 0ULL;
    float mrun = -1e30f, lrun = 0.f;

    const int ktiles = 2 * qt + 2;
    for (int kt = 0; kt < ktiles; kt++) {
        __syncthreads();
        #pragma unroll
        for (int j = 0; j < 32; j++) {
            const size_t krow = (size_t)(kt * 32 + j) * kDH + r;
            Ks[j][r] = kb[krow];
            Vs[j][r] = vb[krow];
        }
        __syncthreads();

        const int climit = qi - kt * 32 + 1;

        float s[32];
        #pragma unroll
        for (int c = 0; c < 32; c++) {
            const ulonglong2* kr = reinterpret_cast<const ulonglong2*>(&Ks[c][0]);
            unsigned long long aa = 0ULL, ab = 0ULL;
            #pragma unroll
            for (int d8 = 0; d8 < 16; d8++) {
                const ulonglong2 kv = kr[d8];
                aa = ffma2(q2[2 * d8 + 0], kv.x, aa);
                ab = ffma2(q2[2 * d8 + 1], kv.y, ab);
            }
            const float2 f = unpack2(fadd2(aa, ab));
            const float acc = f.x + f.y;
            s[c] = (c < climit) ? acc : -1e30f;
        }

        float tmax = -1e30f;
        #pragma unroll
        for (int c = 0; c < 32; c++) tmax = fmaxf(tmax, s[c]);

        const float mnew  = fmaxf(mrun, tmax);
        const float alpha = __expf(mrun - mnew);
        float rowsum = 0.f;
        #pragma unroll
        for (int c = 0; c < 32; c++) {
            const float p = __expf(s[c] - mnew);
            s[c] = p;
            rowsum += p;
        }
        lrun = lrun * alpha + rowsum;
        mrun = mnew;

        const unsigned long long a2 = dup2(alpha);
        #pragma unroll
        for (int i = 0; i < 32; i++) O2[i] = fmul2(O2[i], a2);

        #pragma unroll
        for (int c = 0; c < 32; c++) {
            const unsigned long long p2 = dup2(s[c]);
            const ulonglong2* vr = reinterpret_cast<const ulonglong2*>(&Vs[c][0]);
            #pragma unroll
            for (int d8 = 0; d8 < 16; d8++) {
                const ulonglong2 vv = vr[d8];
                O2[2 * d8 + 0] = ffma2(p2, vv.x, O2[2 * d8 + 0]);
                O2[2 * d8 + 1] = ffma2(p2, vv.y, O2[2 * d8 + 1]);
            }
        }
    }

    const unsigned long long inv2 = dup2(1.f / lrun);
    const int b_ = bh / kH, h = bh % kH;
    float* dstf = g_sa + ((size_t)(b_ * kN + qi)) * kD + h * kDH;
    ulonglong2* dst = reinterpret_cast<ulonglong2*>(dstf);
    #pragma unroll
    for (int i = 0; i < 16; i++) {
        ulonglong2 o;
        o.x = fmul2(O2[2 * i + 0], inv2);
        o.y = fmul2(O2[2 * i + 1], inv2);
        dst[i] = o;
    }
}

// ---------------------------------------------------------------------------
// Kernel 3: output projection. out = sa @ W_proj^T + b_proj  (NT GEMM)
// 128x128x16 tile, 256 threads, 8x8 micro-tile, f32x2 FMA.
// ---------------------------------------------------------------------------
__global__ __launch_bounds__(256) void proj_kernel(const float* __restrict__ Wp,
                                                   const float* __restrict__ bp,
                                                   float* __restrict__ out) {
    const int m0 = blockIdx.x * 128, n0 = blockIdx.y * 128;

    __shared__ __align__(16) float As[16][132];   // As[k][m]
    __shared__ __align__(16) float Bs[16][132];   // Bs[k][n] = Wp[n][k]

    const int tid = threadIdx.x;
    const int ty = tid / 16, tx = tid % 16;

    unsigned long long acc[8][4];
    #pragma unroll
    for (int i = 0; i < 8; i++)
        #pragma unroll
        for (int j = 0; j < 4; j++) acc[i][j] = 0ULL;

    for (int k0 = 0; k0 < kD; k0 += 16) {
        #pragma unroll
        for (int it = 0; it < 2; it++) {
            const int fi = tid + it * 256;
            const int mm = fi >> 2, kq = fi & 3;
            const float4 v = *reinterpret_cast<const float4*>(
                &g_sa[(size_t)(m0 + mm) * kD + k0 + kq * 4]);
            As[kq * 4 + 0][mm] = v.x;
            As[kq * 4 + 1][mm] = v.y;
            As[kq * 4 + 2][mm] = v.z;
            As[kq * 4 + 3][mm] = v.w;
        }
        #pragma unroll
        for (int it = 0; it < 2; it++) {
            const int fi = tid + it * 256;
            const int nn = fi >> 2, kq = fi & 3;
            const float4 v = *reinterpret_cast<const float4*>(
                &Wp[(size_t)(n0 + nn) * kD + k0 + kq * 4]);
            Bs[kq * 4 + 0][nn] = v.x;
            Bs[kq * 4 + 1][nn] = v.y;
            Bs[kq * 4 + 2][nn] = v.z;
            Bs[kq * 4 + 3][nn] = v.w;
        }
        __syncthreads();

        #pragma unroll
        for (int k = 0; k < 16; k++) {
            const float4* apf = reinterpret_cast<const float4*>(&As[k][ty * 8]);
            const float4 a0 = apf[0], a1 = apf[1];
            unsigned long long ad[8];
            ad[0] = dup2(a0.x); ad[1] = dup2(a0.y);
            ad[2] = dup2(a0.z); ad[3] = dup2(a0.w);
            ad[4] = dup2(a1.x); ad[5] = dup2(a1.y);
            ad[6] = dup2(a1.z); ad[7] = dup2(a1.w);

            const ulonglong2* bpv = reinterpret_cast<const ulonglong2*>(&Bs[k][tx * 8]);
            const ulonglong2 b01 = bpv[0], b23 = bpv[1];
            const unsigned long long b2[4] = {b01.x, b01.y, b23.x, b23.y};

            #pragma unroll
            for (int i = 0; i < 8; i++)
                #pragma unroll
                for (int j = 0; j < 4; j++)
                    acc[i][j] = ffma2(ad[i], b2[j], acc[i][j]);
        }
        __syncthreads();
    }

    const int nbase = n0 + tx * 8;
    float b8[8];
    #pragma unroll
    for (int jj = 0; jj < 8; jj++) b8[jj] = bp[nbase + jj];

    #pragma unroll
    for (int i = 0; i < 8; i++) {
        const int m = m0 + ty * 8 + i;
        float o[8];
        #pragma unroll
        for (int j2 = 0; j2 < 4; j2++) {
            const float2 p = unpack2(acc[i][j2]);
            o[2 * j2 + 0] = p.x + b8[2 * j2 + 0];
            o[2 * j2 + 1] = p.y + b8[2 * j2 + 1];
        }
        float* d = out + (size_t)m * kD + nbase;
        *reinterpret_cast<float4*>(d + 0) = make_float4(o[0], o[1], o[2], o[3]);
        *reinterpret_cast<float4*>(d + 4) = make_float4(o[4], o[5], o[6], o[7]);
    }
}

// ---------------------------------------------------------------------------
extern "C" void kernel_launch(void* const* d_in, const int* in_sizes, int n_in,
                              void* d_out, int out_size) {
    (void)in_sizes; (void)n_in; (void)out_size;
    const float* x      = (const float*)d_in[0];
    const float* W_kqv  = (const float*)d_in[1];
    const float* b_kqv  = (const float*)d_in[2];
    const float* W_proj = (const float*)d_in[3];
    const float* b_proj = (const float*)d_in[4];
    float* out = (float*)d_out;

    dim3 gA(kM / 128, kEtot / 128);
    kqv_kernel<<<gA, 256>>>(x, W_kqv, b_kqv);

    dim3 gB(kN / 64, kB * kH);
    attn_kernel<<<gB, 64>>>();

    dim3 gC(kM / 128, kD / 128);
    proj_kernel<<<gC, 256>>>(W_proj, b_proj, out);
}

// round 11
// speedup vs baseline: 1.9697x; 1.3584x over previous
#include <cuda_runtime.h>
#include <cuda_bf16.h>
#include <cstdint>
#include <cstddef>

// Problem constants
namespace {
constexpr int kB  = 2;
constexpr int kN  = 2048;
constexpr int kD  = 1024;
constexpr int kH  = 16;
constexpr int kDH = 64;              // head dim
constexpr int kM  = kB * kN;         // 4096 flattened rows
constexpr int kE  = 3 * kDH;         // 192 per head
constexpr int kEtot = kH * kE;       // 3072 fused kqv columns

constexpr int KC  = 32;              // K chunk (bf16 elems)
constexpr int LDU = 20;              // SMEM row stride in uints (=40 bf16), bank-friendly
}

// Scratch (device globals; no runtime allocation allowed)
__device__ float g_q[kB * kH * kN * kDH];
__device__ float g_k[kB * kH * kN * kDH];
__device__ float g_v[kB * kH * kN * kDH];
__device__ float g_sa[kB * kN * kD];

// ===========================================================================
// mma.sync bf16 (m16n8k16, row.col, fp32 accum) — base sm_103 legal (sm_80+)
// ===========================================================================
__device__ __forceinline__ void mma_bf16(float* d, const uint32_t* a, const uint32_t* b) {
    asm volatile(
        "mma.sync.aligned.m16n8k16.row.col.f32.bf16.bf16.f32 "
        "{%0,%1,%2,%3}, {%4,%5,%6,%7}, {%8,%9}, {%0,%1,%2,%3};"
        : "+f"(d[0]), "+f"(d[1]), "+f"(d[2]), "+f"(d[3])
        : "r"(a[0]), "r"(a[1]), "r"(a[2]), "r"(a[3]), "r"(b[0]), "r"(b[1]));
}

// fp32 pair -> (hi, lo) bf16x2 split
__device__ __forceinline__ void split2(float a, float b, uint32_t& hi, uint32_t& lo) {
    __nv_bfloat16 ha = __float2bfloat16(a), hb = __float2bfloat16(b);
    float ra = a - __bfloat162float(ha);
    float rb = b - __bfloat162float(hb);
    __nv_bfloat16 la = __float2bfloat16(ra), lb = __float2bfloat16(rb);
    hi = (uint32_t)__bfloat16_as_ushort(ha) | ((uint32_t)__bfloat16_as_ushort(hb) << 16);
    lo = (uint32_t)__bfloat16_as_ushort(la) | ((uint32_t)__bfloat16_as_ushort(lb) << 16);
}

// Per-warp compute over one staged K chunk (two k16 steps).
// Warp covers rows [wm*64, wm*64+64), cols [wn*32, wn*32+32).
__device__ __forceinline__ void chunk_mmas(const uint32_t* __restrict__ sAh,
                                           const uint32_t* __restrict__ sAl,
                                           const uint32_t* __restrict__ sBh,
                                           const uint32_t* __restrict__ sBl,
                                           int wm, int wn, int gid, int tig,
                                           float acc[4][4][4]) {
    #pragma unroll
    for (int ks = 0; ks < 2; ks++) {
        uint32_t bh[4][2], bl[4][2];
        #pragma unroll
        for (int nt = 0; nt < 4; nt++) {
            const int n = wn * 32 + nt * 8 + gid;
            const int base = n * LDU + ks * 8 + tig;
            bh[nt][0] = sBh[base];     bh[nt][1] = sBh[base + 4];
            bl[nt][0] = sBl[base];     bl[nt][1] = sBl[base + 4];
        }
        #pragma unroll
        for (int mt = 0; mt < 4; mt++) {
            const int row = wm * 64 + mt * 16 + gid;
            const int ab = row * LDU + ks * 8 + tig;
            uint32_t ah[4], al[4];
            ah[0] = sAh[ab];               ah[1] = sAh[ab + 8 * LDU];
            ah[2] = sAh[ab + 4];           ah[3] = sAh[ab + 8 * LDU + 4];
            al[0] = sAl[ab];               al[1] = sAl[ab + 8 * LDU];
            al[2] = sAl[ab + 4];           al[3] = sAl[ab + 8 * LDU + 4];
            #pragma unroll
            for (int nt = 0; nt < 4; nt++) {
                mma_bf16(acc[mt][nt], ah, bh[nt]);
                mma_bf16(acc[mt][nt], ah, bl[nt]);
                mma_bf16(acc[mt][nt], al, bh[nt]);
            }
        }
    }
}

// ---------------------------------------------------------------------------
// Kernel 1: fused KQV projection, bf16-split tensor-core GEMM.
//   C[m, j] = sum_d x[m,d] * W[h,d,r] + bias_flat[j],  j = h*192 + r
// grid (kM/128, kEtot/128), 256 threads (8 warps, warp grid 2m x 4n).
// ---------------------------------------------------------------------------
__global__ __launch_bounds__(256) void kqv_kernel(const float* __restrict__ x,
                                                  const float* __restrict__ W,
                                                  const float* __restrict__ bias) {
    __shared__ uint32_t sAh[128 * LDU], sAl[128 * LDU];
    __shared__ uint32_t sBh[128 * LDU], sBl[128 * LDU];

    const int tid = threadIdx.x;
    const int wid = tid >> 5, lane = tid & 31;
    const int gid = lane >> 2, tig = lane & 3;
    const int wm = wid & 1, wn = wid >> 1;
    const int m0 = blockIdx.x * 128;
    const int n0 = blockIdx.y * 128;

    // Stage mapping: thread t -> row t/2, k-half t%2 (16 elems)
    const int srow = tid >> 1, shalf = tid & 1;
    const float* aptr = x + (size_t)(m0 + srow) * kD + shalf * 16;
    const int jcol = n0 + srow;                       // output column this thread stages
    const int bh_h = jcol / kE, bh_r = jcol % kE;
    const float* wptr = W + (size_t)bh_h * kD * kE + bh_r;  // elem k at wptr[k*kE]

    float acc[4][4][4];
    #pragma unroll
    for (int i = 0; i < 4; i++)
        #pragma unroll
        for (int j = 0; j < 4; j++)
            #pragma unroll
            for (int r = 0; r < 4; r++) acc[i][j][r] = 0.f;

    for (int ch = 0; ch < kD / KC; ch++) {
        const int k0 = ch * KC;
        // A stage: 16 contiguous floats
        {
            float f[16];
            #pragma unroll
            for (int q = 0; q < 4; q++) {
                const float4 v = *reinterpret_cast<const float4*>(aptr + k0 + q * 4);
                f[q * 4 + 0] = v.x; f[q * 4 + 1] = v.y;
                f[q * 4 + 2] = v.z; f[q * 4 + 3] = v.w;
            }
            #pragma unroll
            for (int j = 0; j < 8; j++) {
                uint32_t h, l;
                split2(f[2 * j], f[2 * j + 1], h, l);
                sAh[srow * LDU + shalf * 8 + j] = h;
                sAl[srow * LDU + shalf * 8 + j] = l;
            }
        }
        // B stage: 16 strided floats (W is [h][k][r], stride kE over k)
        {
            float f[16];
            #pragma unroll
            for (int q = 0; q < 16; q++)
                f[q] = wptr[(size_t)(k0 + shalf * 16 + q) * kE];
            #pragma unroll
            for (int j = 0; j < 8; j++) {
                uint32_t h, l;
                split2(f[2 * j], f[2 * j + 1], h, l);
                sBh[srow * LDU + shalf * 8 + j] = h;
                sBl[srow * LDU + shalf * 8 + j] = l;
            }
        }
        __syncthreads();
        chunk_mmas(sAh, sAl, sBh, sBl, wm, wn, gid, tig, acc);
        __syncthreads();
    }

    // Epilogue: scatter to g_k / g_q / g_v with bias.
    #pragma unroll
    for (int nt = 0; nt < 4; nt++) {
        const int j = n0 + wn * 32 + nt * 8 + tig * 2;
        const int h = j / kE, r = j % kE;
        const int chunk = r / kDH, e = r % kDH;
        float* base = (chunk == 0) ? g_k : (chunk == 1 ? g_q : g_v);
        const float b0 = bias[j], b1 = bias[j + 1];
        #pragma unroll
        for (int mt = 0; mt < 4; mt++) {
            #pragma unroll
            for (int h2 = 0; h2 < 2; h2++) {
                const int row_m = m0 + wm * 64 + mt * 16 + gid + h2 * 8;
                const int b_ = row_m >> 11, n = row_m & (kN - 1);
                float* dst = base + ((size_t)(b_ * kH + h) * kN + n) * kDH + e;
                const float2 o = make_float2(acc[mt][nt][h2 * 2 + 0] + b0,
                                             acc[mt][nt][h2 * 2 + 1] + b1);
                *reinterpret_cast<float2*>(dst) = o;
            }
        }
    }
}

// ---------------------------------------------------------------------------
// Kernel 3: output projection, bf16-split tensor-core GEMM.
//   out[m,n] = sum_k sa[m,k] * Wp[n,k] + bp[n]   (NT; both K-major)
// grid (kM/128, kD/128), 256 threads.
// ---------------------------------------------------------------------------
__global__ __launch_bounds__(256) void proj_kernel(const float* __restrict__ Wp,
                                                   const float* __restrict__ bp,
                                                   float* __restrict__ out) {
    __shared__ uint32_t sAh[128 * LDU], sAl[128 * LDU];
    __shared__ uint32_t sBh[128 * LDU], sBl[128 * LDU];

    const int tid = threadIdx.x;
    const int wid = tid >> 5, lane = tid & 31;
    const int gid = lane >> 2, tig = lane & 3;
    const int wm = wid & 1, wn = wid >> 1;
    const int m0 = blockIdx.x * 128;
    const int n0 = blockIdx.y * 128;

    const int srow = tid >> 1, shalf = tid & 1;
    const float* aptr = g_sa + (size_t)(m0 + srow) * kD + shalf * 16;
    const float* wptr = Wp + (size_t)(n0 + srow) * kD + shalf * 16;

    float acc[4][4][4];
    #pragma unroll
    for (int i = 0; i < 4; i++)
        #pragma unroll
        for (int j = 0; j < 4; j++)
            #pragma unroll
            for (int r = 0; r < 4; r++) acc[i][j][r] = 0.f;

    for (int ch = 0; ch < kD / KC; ch++) {
        const int k0 = ch * KC;
        {
            float f[16];
            #pragma unroll
            for (int q = 0; q < 4; q++) {
                const float4 v = *reinterpret_cast<const float4*>(aptr + k0 + q * 4);
                f[q * 4 + 0] = v.x; f[q * 4 + 1] = v.y;
                f[q * 4 + 2] = v.z; f[q * 4 + 3] = v.w;
            }
            #pragma unroll
            for (int j = 0; j < 8; j++) {
                uint32_t h, l;
                split2(f[2 * j], f[2 * j + 1], h, l);
                sAh[srow * LDU + shalf * 8 + j] = h;
                sAl[srow * LDU + shalf * 8 + j] = l;
            }
        }
        {
            float f[16];
            #pragma unroll
            for (int q = 0; q < 4; q++) {
                const float4 v = *reinterpret_cast<const float4*>(wptr + k0 + q * 4);
                f[q * 4 + 0] = v.x; f[q * 4 + 1] = v.y;
                f[q * 4 + 2] = v.z; f[q * 4 + 3] = v.w;
            }
            #pragma unroll
            for (int j = 0; j < 8; j++) {
                uint32_t h, l;
                split2(f[2 * j], f[2 * j + 1], h, l);
                sBh[srow * LDU + shalf * 8 + j] = h;
                sBl[srow * LDU + shalf * 8 + j] = l;
            }
        }
        __syncthreads();
        chunk_mmas(sAh, sAl, sBh, sBl, wm, wn, gid, tig, acc);
        __syncthreads();
    }

    #pragma unroll
    for (int nt = 0; nt < 4; nt++) {
        const int n = n0 + wn * 32 + nt * 8 + tig * 2;
        const float b0 = bp[n], b1 = bp[n + 1];
        #pragma unroll
        for (int mt = 0; mt < 4; mt++) {
            #pragma unroll
            for (int h2 = 0; h2 < 2; h2++) {
                const int row_m = m0 + wm * 64 + mt * 16 + gid + h2 * 8;
                float* dst = out + (size_t)row_m * kD + n;
                const float2 o = make_float2(acc[mt][nt][h2 * 2 + 0] + b0,
                                             acc[mt][nt][h2 * 2 + 1] + b1);
                *reinterpret_cast<float2*>(dst) = o;
            }
        }
    }
}

// ---------------------------------------------------------------------------
// Kernel 2: causal flash attention per (b,h), f32x2 inner loops (R8, passing).
// ---------------------------------------------------------------------------
__device__ __forceinline__ unsigned long long ffma2(unsigned long long a,
                                                    unsigned long long b,
                                                    unsigned long long c) {
    unsigned long long d;
    asm("fma.rn.f32x2 %0, %1, %2, %3;" : "=l"(d) : "l"(a), "l"(b), "l"(c));
    return d;
}
__device__ __forceinline__ unsigned long long fmul2(unsigned long long a,
                                                    unsigned long long b) {
    unsigned long long d;
    asm("mul.rn.f32x2 %0, %1, %2;" : "=l"(d) : "l"(a), "l"(b));
    return d;
}
__device__ __forceinline__ unsigned long long fadd2(unsigned long long a,
                                                    unsigned long long b) {
    unsigned long long d;
    asm("add.rn.f32x2 %0, %1, %2;" : "=l"(d) : "l"(a), "l"(b));
    return d;
}
__device__ __forceinline__ unsigned long long dup2(float a) {
    unsigned long long r;
    unsigned int u = __float_as_uint(a);
    asm("mov.b64 %0, {%1, %1};" : "=l"(r) : "r"(u));
    return r;
}
__device__ __forceinline__ float2 unpack2(unsigned long long v) {
    float2 r;
    asm("mov.b64 {%0, %1}, %2;" : "=f"(r.x), "=f"(r.y) : "l"(v));
    return r;
}

__global__ __launch_bounds__(64) void attn_kernel() {
    const int qt = gridDim.x - 1 - blockIdx.x;   // heavy blocks first
    const int bh = blockIdx.y;
    const int r  = threadIdx.x;
    const int qi = qt * 64 + r;

    const float* qb = g_q + (size_t)bh * kN * kDH;
    const float* kb = g_k + (size_t)bh * kN * kDH;
    const float* vb = g_v + (size_t)bh * kN * kDH;

    __shared__ __align__(16) float Ks[32][64];
    __shared__ __align__(16) float Vs[32][64];

    unsigned long long q2[32];
    {
        const ulonglong2* qr = reinterpret_cast<const ulonglong2*>(qb + (size_t)qi * kDH);
        const unsigned long long sc = dup2(0.125f);
        #pragma unroll
        for (int i = 0; i < 16; i++) {
            const ulonglong2 t = qr[i];
            q2[2 * i + 0] = fmul2(t.x, sc);
            q2[2 * i + 1] = fmul2(t.y, sc);
        }
    }

    unsigned long long O2[32];
    #pragma unroll
    for (int i = 0; i < 32; i++) O2[i] = 0ULL;
    float mrun = -1e30f, lrun = 0.f;

    const int ktiles = 2 * qt + 2;
    for (int kt = 0; kt < ktiles; kt++) {
        __syncthreads();
        #pragma unroll
        for (int j = 0; j < 32; j++) {
            const size_t krow = (size_t)(kt * 32 + j) * kDH + r;
            Ks[j][r] = kb[krow];
            Vs[j][r] = vb[krow];
        }
        __syncthreads();

        const int climit = qi - kt * 32 + 1;

        float s[32];
        #pragma unroll
        for (int c = 0; c < 32; c++) {
            const ulonglong2* kr = reinterpret_cast<const ulonglong2*>(&Ks[c][0]);
            unsigned long long aa = 0ULL, ab = 0ULL;
            #pragma unroll
            for (int d8 = 0; d8 < 16; d8++) {
                const ulonglong2 kv = kr[d8];
                aa = ffma2(q2[2 * d8 + 0], kv.x, aa);
                ab = ffma2(q2[2 * d8 + 1], kv.y, ab);
            }
            const float2 f = unpack2(fadd2(aa, ab));
            const float acc = f.x + f.y;
            s[c] = (c < climit) ? acc : -1e30f;
        }

        float tmax = -1e30f;
        #pragma unroll
        for (int c = 0; c < 32; c++) tmax = fmaxf(tmax, s[c]);

        const float mnew  = fmaxf(mrun, tmax);
        const float alpha = __expf(mrun - mnew);
        float rowsum = 0.f;
        #pragma unroll
        for (int c = 0; c < 32; c++) {
            const float p = __expf(s[c] - mnew);
            s[c] = p;
            rowsum += p;
        }
        lrun = lrun * alpha + rowsum;
        mrun = mnew;

        const unsigned long long a2 = dup2(alpha);
        #pragma unroll
        for (int i = 0; i < 32; i++) O2[i] = fmul2(O2[i], a2);

        #pragma unroll
        for (int c = 0; c < 32; c++) {
            const unsigned long long p2 = dup2(s[c]);
            const ulonglong2* vr = reinterpret_cast<const ulonglong2*>(&Vs[c][0]);
            #pragma unroll
            for (int d8 = 0; d8 < 16; d8++) {
                const ulonglong2 vv = vr[d8];
                O2[2 * d8 + 0] = ffma2(p2, vv.x, O2[2 * d8 + 0]);
                O2[2 * d8 + 1] = ffma2(p2, vv.y, O2[2 * d8 + 1]);
            }
        }
    }

    const unsigned long long inv2 = dup2(1.f / lrun);
    const int b_ = bh / kH, h = bh % kH;
    float* dstf = g_sa + ((size_t)(b_ * kN + qi)) * kD + h * kDH;
    ulonglong2* dst = reinterpret_cast<ulonglong2*>(dstf);
    #pragma unroll
    for (int i = 0; i < 16; i++) {
        ulonglong2 o;
        o.x = fmul2(O2[2 * i + 0], inv2);
        o.y = fmul2(O2[2 * i + 1], inv2);
        dst[i] = o;
    }
}

// ---------------------------------------------------------------------------
extern "C" void kernel_launch(void* const* d_in, const int* in_sizes, int n_in,
                              void* d_out, int out_size) {
    (void)in_sizes; (void)n_in; (void)out_size;
    const float* x      = (const float*)d_in[0];
    const float* W_kqv  = (const float*)d_in[1];
    const float* b_kqv  = (const float*)d_in[2];
    const float* W_proj = (const float*)d_in[3];
    const float* b_proj = (const float*)d_in[4];
    float* out = (float*)d_out;

    dim3 gA(kM / 128, kEtot / 128);
    kqv_kernel<<<gA, 256>>>(x, W_kqv, b_kqv);

    dim3 gB(kN / 64, kB * kH);
    attn_kernel<<<gB, 64>>>();

    dim3 gC(kM / 128, kD / 128);
    proj_kernel<<<gC, 256>>>(W_proj, b_proj, out);
}

// round 12
// speedup vs baseline: 3.2498x; 1.6499x over previous
#include <cuda_runtime.h>
#include <cuda_bf16.h>
#include <cstdint>
#include <cstddef>

// Problem constants
namespace {
constexpr int kB  = 2;
constexpr int kN  = 2048;
constexpr int kD  = 1024;
constexpr int kH  = 16;
constexpr int kDH = 64;              // head dim
constexpr int kM  = kB * kN;         // 4096 flattened rows
constexpr int kE  = 3 * kDH;         // 192 per head
constexpr int kEtot = kH * kE;       // 3072 fused kqv columns

constexpr int KC  = 32;              // K chunk (bf16 elems) for dense GEMMs
constexpr int LDU = 20;              // GEMM SMEM row stride in uints
constexpr int ALD = 36;              // attention SMEM row stride in uints (64 dh/keys = 32 uints + pad)
}

// Scratch (device globals; no runtime allocation allowed)
__device__ float g_q[kB * kH * kN * kDH];
__device__ float g_k[kB * kH * kN * kDH];
__device__ float g_v[kB * kH * kN * kDH];
__device__ float g_sa[kB * kN * kD];

// ===========================================================================
// mma.sync bf16 (m16n8k16, row.col, fp32 accum) — base sm_103 legal (sm_80+)
// ===========================================================================
__device__ __forceinline__ void mma_bf16(float* d, const uint32_t* a, const uint32_t* b) {
    asm volatile(
        "mma.sync.aligned.m16n8k16.row.col.f32.bf16.bf16.f32 "
        "{%0,%1,%2,%3}, {%4,%5,%6,%7}, {%8,%9}, {%0,%1,%2,%3};"
        : "+f"(d[0]), "+f"(d[1]), "+f"(d[2]), "+f"(d[3])
        : "r"(a[0]), "r"(a[1]), "r"(a[2]), "r"(a[3]), "r"(b[0]), "r"(b[1]));
}

// fp32 pair -> (hi, lo) bf16x2 split
__device__ __forceinline__ void split2(float a, float b, uint32_t& hi, uint32_t& lo) {
    __nv_bfloat16 ha = __float2bfloat16(a), hb = __float2bfloat16(b);
    float ra = a - __bfloat162float(ha);
    float rb = b - __bfloat162float(hb);
    __nv_bfloat16 la = __float2bfloat16(ra), lb = __float2bfloat16(rb);
    hi = (uint32_t)__bfloat16_as_ushort(ha) | ((uint32_t)__bfloat16_as_ushort(hb) << 16);
    lo = (uint32_t)__bfloat16_as_ushort(la) | ((uint32_t)__bfloat16_as_ushort(lb) << 16);
}

// ===========================================================================
// Dense GEMM machinery (unchanged from R11, passing)
// ===========================================================================
__device__ __forceinline__ void chunk_mmas(const uint32_t* __restrict__ sAh,
                                           const uint32_t* __restrict__ sAl,
                                           const uint32_t* __restrict__ sBh,
                                           const uint32_t* __restrict__ sBl,
                                           int wm, int wn, int gid, int tig,
                                           float acc[4][4][4]) {
    #pragma unroll
    for (int ks = 0; ks < 2; ks++) {
        uint32_t bh[4][2], bl[4][2];
        #pragma unroll
        for (int nt = 0; nt < 4; nt++) {
            const int n = wn * 32 + nt * 8 + gid;
            const int base = n * LDU + ks * 8 + tig;
            bh[nt][0] = sBh[base];     bh[nt][1] = sBh[base + 4];
            bl[nt][0] = sBl[base];     bl[nt][1] = sBl[base + 4];
        }
        #pragma unroll
        for (int mt = 0; mt < 4; mt++) {
            const int row = wm * 64 + mt * 16 + gid;
            const int ab = row * LDU + ks * 8 + tig;
            uint32_t ah[4], al[4];
            ah[0] = sAh[ab];               ah[1] = sAh[ab + 8 * LDU];
            ah[2] = sAh[ab + 4];           ah[3] = sAh[ab + 8 * LDU + 4];
            al[0] = sAl[ab];               al[1] = sAl[ab + 8 * LDU];
            al[2] = sAl[ab + 4];           al[3] = sAl[ab + 8 * LDU + 4];
            #pragma unroll
            for (int nt = 0; nt < 4; nt++) {
                mma_bf16(acc[mt][nt], ah, bh[nt]);
                mma_bf16(acc[mt][nt], ah, bl[nt]);
                mma_bf16(acc[mt][nt], al, bh[nt]);
            }
        }
    }
}

// ---------------------------------------------------------------------------
// Kernel 1: fused KQV projection, bf16-split tensor-core GEMM.
// ---------------------------------------------------------------------------
__global__ __launch_bounds__(256) void kqv_kernel(const float* __restrict__ x,
                                                  const float* __restrict__ W,
                                                  const float* __restrict__ bias) {
    __shared__ uint32_t sAh[128 * LDU], sAl[128 * LDU];
    __shared__ uint32_t sBh[128 * LDU], sBl[128 * LDU];

    const int tid = threadIdx.x;
    const int wid = tid >> 5, lane = tid & 31;
    const int gid = lane >> 2, tig = lane & 3;
    const int wm = wid & 1, wn = wid >> 1;
    const int m0 = blockIdx.x * 128;
    const int n0 = blockIdx.y * 128;

    const int srow = tid >> 1, shalf = tid & 1;
    const float* aptr = x + (size_t)(m0 + srow) * kD + shalf * 16;
    const int jcol = n0 + srow;
    const int bh_h = jcol / kE, bh_r = jcol % kE;
    const float* wptr = W + (size_t)bh_h * kD * kE + bh_r;

    float acc[4][4][4];
    #pragma unroll
    for (int i = 0; i < 4; i++)
        #pragma unroll
        for (int j = 0; j < 4; j++)
            #pragma unroll
            for (int r = 0; r < 4; r++) acc[i][j][r] = 0.f;

    for (int ch = 0; ch < kD / KC; ch++) {
        const int k0 = ch * KC;
        {
            float f[16];
            #pragma unroll
            for (int q = 0; q < 4; q++) {
                const float4 v = *reinterpret_cast<const float4*>(aptr + k0 + q * 4);
                f[q * 4 + 0] = v.x; f[q * 4 + 1] = v.y;
                f[q * 4 + 2] = v.z; f[q * 4 + 3] = v.w;
            }
            #pragma unroll
            for (int j = 0; j < 8; j++) {
                uint32_t h, l;
                split2(f[2 * j], f[2 * j + 1], h, l);
                sAh[srow * LDU + shalf * 8 + j] = h;
                sAl[srow * LDU + shalf * 8 + j] = l;
            }
        }
        {
            float f[16];
            #pragma unroll
            for (int q = 0; q < 16; q++)
                f[q] = wptr[(size_t)(k0 + shalf * 16 + q) * kE];
            #pragma unroll
            for (int j = 0; j < 8; j++) {
                uint32_t h, l;
                split2(f[2 * j], f[2 * j + 1], h, l);
                sBh[srow * LDU + shalf * 8 + j] = h;
                sBl[srow * LDU + shalf * 8 + j] = l;
            }
        }
        __syncthreads();
        chunk_mmas(sAh, sAl, sBh, sBl, wm, wn, gid, tig, acc);
        __syncthreads();
    }

    #pragma unroll
    for (int nt = 0; nt < 4; nt++) {
        const int j = n0 + wn * 32 + nt * 8 + tig * 2;
        const int h = j / kE, r = j % kE;
        const int chunk = r / kDH, e = r % kDH;
        float* base = (chunk == 0) ? g_k : (chunk == 1 ? g_q : g_v);
        const float b0 = bias[j], b1 = bias[j + 1];
        #pragma unroll
        for (int mt = 0; mt < 4; mt++) {
            #pragma unroll
            for (int h2 = 0; h2 < 2; h2++) {
                const int row_m = m0 + wm * 64 + mt * 16 + gid + h2 * 8;
                const int b_ = row_m >> 11, n = row_m & (kN - 1);
                float* dst = base + ((size_t)(b_ * kH + h) * kN + n) * kDH + e;
                const float2 o = make_float2(acc[mt][nt][h2 * 2 + 0] + b0,
                                             acc[mt][nt][h2 * 2 + 1] + b1);
                *reinterpret_cast<float2*>(dst) = o;
            }
        }
    }
}

// ---------------------------------------------------------------------------
// Kernel 3: output projection, bf16-split tensor-core GEMM (unchanged).
// ---------------------------------------------------------------------------
__global__ __launch_bounds__(256) void proj_kernel(const float* __restrict__ Wp,
                                                   const float* __restrict__ bp,
                                                   float* __restrict__ out) {
    __shared__ uint32_t sAh[128 * LDU], sAl[128 * LDU];
    __shared__ uint32_t sBh[128 * LDU], sBl[128 * LDU];

    const int tid = threadIdx.x;
    const int wid = tid >> 5, lane = tid & 31;
    const int gid = lane >> 2, tig = lane & 3;
    const int wm = wid & 1, wn = wid >> 1;
    const int m0 = blockIdx.x * 128;
    const int n0 = blockIdx.y * 128;

    const int srow = tid >> 1, shalf = tid & 1;
    const float* aptr = g_sa + (size_t)(m0 + srow) * kD + shalf * 16;
    const float* wptr = Wp + (size_t)(n0 + srow) * kD + shalf * 16;

    float acc[4][4][4];
    #pragma unroll
    for (int i = 0; i < 4; i++)
        #pragma unroll
        for (int j = 0; j < 4; j++)
            #pragma unroll
            for (int r = 0; r < 4; r++) acc[i][j][r] = 0.f;

    for (int ch = 0; ch < kD / KC; ch++) {
        const int k0 = ch * KC;
        {
            float f[16];
            #pragma unroll
            for (int q = 0; q < 4; q++) {
                const float4 v = *reinterpret_cast<const float4*>(aptr + k0 + q * 4);
                f[q * 4 + 0] = v.x; f[q * 4 + 1] = v.y;
                f[q * 4 + 2] = v.z; f[q * 4 + 3] = v.w;
            }
            #pragma unroll
            for (int j = 0; j < 8; j++) {
                uint32_t h, l;
                split2(f[2 * j], f[2 * j + 1], h, l);
                sAh[srow * LDU + shalf * 8 + j] = h;
                sAl[srow * LDU + shalf * 8 + j] = l;
            }
        }
        {
            float f[16];
            #pragma unroll
            for (int q = 0; q < 4; q++) {
                const float4 v = *reinterpret_cast<const float4*>(wptr + k0 + q * 4);
                f[q * 4 + 0] = v.x; f[q * 4 + 1] = v.y;
                f[q * 4 + 2] = v.z; f[q * 4 + 3] = v.w;
            }
            #pragma unroll
            for (int j = 0; j < 8; j++) {
                uint32_t h, l;
                split2(f[2 * j], f[2 * j + 1], h, l);
                sBh[srow * LDU + shalf * 8 + j] = h;
                sBl[srow * LDU + shalf * 8 + j] = l;
            }
        }
        __syncthreads();
        chunk_mmas(sAh, sAl, sBh, sBl, wm, wn, gid, tig, acc);
        __syncthreads();
    }

    #pragma unroll
    for (int nt = 0; nt < 4; nt++) {
        const int n = n0 + wn * 32 + nt * 8 + tig * 2;
        const float b0 = bp[n], b1 = bp[n + 1];
        #pragma unroll
        for (int mt = 0; mt < 4; mt++) {
            #pragma unroll
            for (int h2 = 0; h2 < 2; h2++) {
                const int row_m = m0 + wm * 64 + mt * 16 + gid + h2 * 8;
                float* dst = out + (size_t)row_m * kD + n;
                const float2 o = make_float2(acc[mt][nt][h2 * 2 + 0] + b0,
                                             acc[mt][nt][h2 * 2 + 1] + b1);
                *reinterpret_cast<float2*>(dst) = o;
            }
        }
    }
}

// ---------------------------------------------------------------------------
// Kernel 2: tensor-core causal flash attention (NEW).
// grid (kN/128, kB*kH), 256 threads (8 warps x 16 query rows).
// Key tiles of 64. K staged [key][dh] hi/lo; V staged transposed [dh][key].
// ---------------------------------------------------------------------------
__global__ __launch_bounds__(256, 2) void attn_kernel() {
    __shared__ uint32_t sKh[64 * ALD], sKl[64 * ALD];
    __shared__ uint32_t sVh[64 * ALD], sVl[64 * ALD];   // transposed: [dh][key pairs]

    const int qb  = gridDim.x - 1 - blockIdx.x;          // heavy blocks first
    const int bh  = blockIdx.y;
    const int tid = threadIdx.x;
    const int wid = tid >> 5, lane = tid & 31;
    const int gid = lane >> 2, tig = lane & 3;
    const int rb  = qb * 128 + wid * 16;                 // warp's first query row

    const float* qptr = g_q + (size_t)bh * kN * kDH;
    const float* kptr = g_k + (size_t)bh * kN * kDH;
    const float* vptr = g_v + (size_t)bh * kN * kDH;

    // --- Q fragments (held for whole kernel), pre-scaled by 1/8, split ---
    uint32_t qh[4][4], ql[4][4];
    {
        const float* q0 = qptr + (size_t)(rb + gid) * kDH;
        const float* q1 = qptr + (size_t)(rb + gid + 8) * kDH;
        #pragma unroll
        for (int ks = 0; ks < 4; ks++) {
            float2 x;
            x = *reinterpret_cast<const float2*>(q0 + ks * 16 + tig * 2);
            split2(x.x * 0.125f, x.y * 0.125f, qh[ks][0], ql[ks][0]);
            x = *reinterpret_cast<const float2*>(q1 + ks * 16 + tig * 2);
            split2(x.x * 0.125f, x.y * 0.125f, qh[ks][1], ql[ks][1]);
            x = *reinterpret_cast<const float2*>(q0 + ks * 16 + 8 + tig * 2);
            split2(x.x * 0.125f, x.y * 0.125f, qh[ks][2], ql[ks][2]);
            x = *reinterpret_cast<const float2*>(q1 + ks * 16 + 8 + tig * 2);
            split2(x.x * 0.125f, x.y * 0.125f, qh[ks][3], ql[ks][3]);
        }
    }

    float O[8][4];
    #pragma unroll
    for (int i = 0; i < 8; i++)
        #pragma unroll
        for (int c = 0; c < 4; c++) O[i][c] = 0.f;
    float m0 = -1e30f, m1 = -1e30f, l0 = 0.f, l1 = 0.f;

    const int ktiles = 2 * qb + 2;
    const int kd = 2 * qb + (wid >> 2);                  // warp's diagonal key tile

    // staging mapping: thread -> key row tid>>2, 16-float quarter tid&3
    const int skey = tid >> 2, spart = tid & 3;

    for (int kt = 0; kt < ktiles; kt++) {
        __syncthreads();
        {   // stage K (pairs along dh) and V transposed (pairs along key), hi/lo
            const float* kr = kptr + (size_t)(kt * 64 + skey) * kDH + spart * 16;
            const float* vr = vptr + (size_t)(kt * 64 + skey) * kDH + spart * 16;
            float fk[16], fv[16];
            #pragma unroll
            for (int q = 0; q < 4; q++) {
                const float4 a = *reinterpret_cast<const float4*>(kr + q * 4);
                fk[q * 4 + 0] = a.x; fk[q * 4 + 1] = a.y;
                fk[q * 4 + 2] = a.z; fk[q * 4 + 3] = a.w;
                const float4 b = *reinterpret_cast<const float4*>(vr + q * 4);
                fv[q * 4 + 0] = b.x; fv[q * 4 + 1] = b.y;
                fv[q * 4 + 2] = b.z; fv[q * 4 + 3] = b.w;
            }
            #pragma unroll
            for (int j = 0; j < 8; j++) {
                uint32_t h, l;
                split2(fk[2 * j], fk[2 * j + 1], h, l);
                sKh[skey * ALD + spart * 8 + j] = h;
                sKl[skey * ALD + spart * 8 + j] = l;
            }
            __nv_bfloat16* bVh = reinterpret_cast<__nv_bfloat16*>(sVh);
            __nv_bfloat16* bVl = reinterpret_cast<__nv_bfloat16*>(sVl);
            #pragma unroll
            for (int j = 0; j < 16; j++) {
                const float f = fv[j];
                const __nv_bfloat16 h = __float2bfloat16(f);
                const __nv_bfloat16 l = __float2bfloat16(f - __bfloat162float(h));
                const int dh = spart * 16 + j;
                bVh[dh * (2 * ALD) + skey] = h;
                bVl[dh * (2 * ALD) + skey] = l;
            }
        }
        __syncthreads();

        if (kt > kd) continue;                           // fully masked for this warp

        // --- S = Q K^T (split: hh + hl + lh) ---
        float S[8][4];
        #pragma unroll
        for (int i = 0; i < 8; i++)
            #pragma unroll
            for (int c = 0; c < 4; c++) S[i][c] = 0.f;
        #pragma unroll
        for (int nt = 0; nt < 8; nt++) {
            #pragma unroll
            for (int ks = 0; ks < 4; ks++) {
                const int base = (nt * 8 + gid) * ALD + ks * 8 + tig;
                uint32_t bhr[2] = {sKh[base], sKh[base + 4]};
                uint32_t blr[2] = {sKl[base], sKl[base + 4]};
                mma_bf16(S[nt], qh[ks], bhr);
                mma_bf16(S[nt], qh[ks], blr);
                mma_bf16(S[nt], ql[ks], bhr);
            }
        }

        // --- causal mask on diagonal tile ---
        if (kt == kd) {
            #pragma unroll
            for (int nt = 0; nt < 8; nt++) {
                #pragma unroll
                for (int c = 0; c < 4; c++) {
                    const int row = rb + gid + (c >> 1) * 8;
                    const int col = kt * 64 + nt * 8 + tig * 2 + (c & 1);
                    if (col > row) S[nt][c] = -1e30f;
                }
            }
        }

        // --- online softmax (rows: gid -> c0,c1 ; gid+8 -> c2,c3) ---
        float mx0 = -1e30f, mx1 = -1e30f;
        #pragma unroll
        for (int nt = 0; nt < 8; nt++) {
            mx0 = fmaxf(mx0, fmaxf(S[nt][0], S[nt][1]));
            mx1 = fmaxf(mx1, fmaxf(S[nt][2], S[nt][3]));
        }
        mx0 = fmaxf(mx0, __shfl_xor_sync(0xffffffffu, mx0, 1));
        mx0 = fmaxf(mx0, __shfl_xor_sync(0xffffffffu, mx0, 2));
        mx1 = fmaxf(mx1, __shfl_xor_sync(0xffffffffu, mx1, 1));
        mx1 = fmaxf(mx1, __shfl_xor_sync(0xffffffffu, mx1, 2));

        const float mn0 = fmaxf(m0, mx0), mn1 = fmaxf(m1, mx1);
        const float al0 = __expf(m0 - mn0), al1 = __expf(m1 - mn1);
        m0 = mn0; m1 = mn1;

        float s0 = 0.f, s1 = 0.f;
        #pragma unroll
        for (int nt = 0; nt < 8; nt++) {
            S[nt][0] = __expf(S[nt][0] - mn0); s0 += S[nt][0];
            S[nt][1] = __expf(S[nt][1] - mn0); s0 += S[nt][1];
            S[nt][2] = __expf(S[nt][2] - mn1); s1 += S[nt][2];
            S[nt][3] = __expf(S[nt][3] - mn1); s1 += S[nt][3];
        }
        s0 += __shfl_xor_sync(0xffffffffu, s0, 1);
        s0 += __shfl_xor_sync(0xffffffffu, s0, 2);
        s1 += __shfl_xor_sync(0xffffffffu, s1, 1);
        s1 += __shfl_xor_sync(0xffffffffu, s1, 2);
        l0 = l0 * al0 + s0;
        l1 = l1 * al1 + s1;

        #pragma unroll
        for (int nt = 0; nt < 8; nt++) {
            O[nt][0] *= al0; O[nt][1] *= al0;
            O[nt][2] *= al1; O[nt][3] *= al1;
        }

        // --- O += P V (P split in registers; A-frags straight from S acc) ---
        #pragma unroll
        for (int ks = 0; ks < 4; ks++) {
            uint32_t ah[4], al_[4];
            split2(S[2 * ks][0],     S[2 * ks][1],     ah[0], al_[0]);
            split2(S[2 * ks][2],     S[2 * ks][3],     ah[1], al_[1]);
            split2(S[2 * ks + 1][0], S[2 * ks + 1][1], ah[2], al_[2]);
            split2(S[2 * ks + 1][2], S[2 * ks + 1][3], ah[3], al_[3]);
            #pragma unroll
            for (int nt = 0; nt < 8; nt++) {
                const int base = (nt * 8 + gid) * ALD + ks * 8 + tig;
                uint32_t bhr[2] = {sVh[base], sVh[base + 4]};
                uint32_t blr[2] = {sVl[base], sVl[base + 4]};
                mma_bf16(O[nt], ah, bhr);
                mma_bf16(O[nt], ah, blr);
                mma_bf16(O[nt], al_, bhr);
            }
        }
    }

    // --- epilogue: normalize and write head-concat layout ---
    const float inv0 = 1.f / l0, inv1 = 1.f / l1;
    const int b_ = bh / kH, h = bh % kH;
    float* o0 = g_sa + ((size_t)(b_ * kN) + rb + gid) * kD + h * kDH;
    float* o1 = g_sa + ((size_t)(b_ * kN) + rb + gid + 8) * kD + h * kDH;
    #pragma unroll
    for (int nt = 0; nt < 8; nt++) {
        *reinterpret_cast<float2*>(o0 + nt * 8 + tig * 2) =
            make_float2(O[nt][0] * inv0, O[nt][1] * inv0);
        *reinterpret_cast<float2*>(o1 + nt * 8 + tig * 2) =
            make_float2(O[nt][2] * inv1, O[nt][3] * inv1);
    }
}

// ---------------------------------------------------------------------------
extern "C" void kernel_launch(void* const* d_in, const int* in_sizes, int n_in,
                              void* d_out, int out_size) {
    (void)in_sizes; (void)n_in; (void)out_size;
    const float* x      = (const float*)d_in[0];
    const float* W_kqv  = (const float*)d_in[1];
    const float* b_kqv  = (const float*)d_in[2];
    const float* W_proj = (const float*)d_in[3];
    const float* b_proj = (const float*)d_in[4];
    float* out = (float*)d_out;

    dim3 gA(kM / 128, kEtot / 128);
    kqv_kernel<<<gA, 256>>>(x, W_kqv, b_kqv);

    dim3 gB(kN / 128, kB * kH);
    attn_kernel<<<gB, 256>>>();

    dim3 gC(kM / 128, kD / 128);
    proj_kernel<<<gC, 256>>>(W_proj, b_proj, out);
}

// round 16
// speedup vs baseline: 3.8159x; 1.1742x over previous
#include <cuda_runtime.h>
#include <cuda_bf16.h>
#include <cstdint>
#include <cstddef>

// Problem constants
namespace {
constexpr int kB  = 2;
constexpr int kN  = 2048;
constexpr int kD  = 1024;
constexpr int kH  = 16;
constexpr int kDH = 64;
constexpr int kM  = kB * kN;         // 4096
constexpr int kE  = 3 * kDH;         // 192
constexpr int kEtot = kH * kE;       // 3072

constexpr int LDU  = 20;             // GEMM smem row stride (uints)
constexpr int ALD  = 36;             // attention smem row stride (uints)
constexpr int ROWU = kD / 2;         // 512 packed uints per 1024-elem row
constexpr int TILEU = 128 * LDU;     // 2560 uints per tile array
constexpr int GEMM_SMEM = 2 * 4 * TILEU * 4;   // 81920 B dynamic smem
constexpr int NCH = kD / 32;         // 32 K-chunks of 32
}

// ---------------------------------------------------------------------------
// Pre-split packed bf16 hi/lo pair buffers (device globals; no runtime alloc)
// ---------------------------------------------------------------------------
__device__ uint32_t g_xh[kM * ROWU],    g_xl[kM * ROWU];       // x rows
__device__ uint32_t g_wth[kEtot * ROWU], g_wtl[kEtot * ROWU];  // W_kqv^T rows [j][k]
__device__ uint32_t g_wph[kD * ROWU],   g_wpl[kD * ROWU];      // W_proj rows [n][k]
__device__ uint32_t g_qh[kB * kH * kN * 32], g_ql[kB * kH * kN * 32];
__device__ uint32_t g_kh[kB * kH * kN * 32], g_kl[kB * kH * kN * 32];
__device__ uint32_t g_vh[kB * kH * kN * 32], g_vl[kB * kH * kN * 32];
__device__ uint32_t g_sah[kM * ROWU],   g_sal[kM * ROWU];      // attention out rows

// ===========================================================================
// Helpers
// ===========================================================================
__device__ __forceinline__ void mma_bf16(float* d, const uint32_t* a, const uint32_t* b) {
    asm volatile(
        "mma.sync.aligned.m16n8k16.row.col.f32.bf16.bf16.f32 "
        "{%0,%1,%2,%3}, {%4,%5,%6,%7}, {%8,%9}, {%0,%1,%2,%3};"
        : "+f"(d[0]), "+f"(d[1]), "+f"(d[2]), "+f"(d[3])
        : "r"(a[0]), "r"(a[1]), "r"(a[2]), "r"(a[3]), "r"(b[0]), "r"(b[1]));
}

__device__ __forceinline__ void split2(float a, float b, uint32_t& hi, uint32_t& lo) {
    __nv_bfloat16 ha = __float2bfloat16(a), hb = __float2bfloat16(b);
    float ra = a - __bfloat162float(ha);
    float rb = b - __bfloat162float(hb);
    __nv_bfloat16 la = __float2bfloat16(ra), lb = __float2bfloat16(rb);
    hi = (uint32_t)__bfloat16_as_ushort(ha) | ((uint32_t)__bfloat16_as_ushort(hb) << 16);
    lo = (uint32_t)__bfloat16_as_ushort(la) | ((uint32_t)__bfloat16_as_ushort(lb) << 16);
}

__device__ __forceinline__ uint32_t smem_u32(const void* p) {
    uint32_t a;
    asm("{ .reg .u64 t; cvta.to.shared.u64 t, %1; cvt.u32.u64 %0, t; }" : "=r"(a) : "l"(p));
    return a;
}
__device__ __forceinline__ void cpa16(uint32_t dst, const uint32_t* src) {
    asm volatile("cp.async.cg.shared.global [%0], [%1], 16;" :: "r"(dst), "l"(src));
}
__device__ __forceinline__ void cpa_commit() {
    asm volatile("cp.async.commit_group;" ::: "memory");
}
template <int N>
__device__ __forceinline__ void cpa_wait() {
    asm volatile("cp.async.wait_group %0;" :: "n"(N) : "memory");
}

// ===========================================================================
// Pre-split kernels
// ===========================================================================
__global__ __launch_bounds__(256) void split_x_kernel(const float* __restrict__ x) {
    const int i = blockIdx.x * 256 + threadIdx.x;          // pair index
    const float2 v = reinterpret_cast<const float2*>(x)[i];
    uint32_t h, l;
    split2(v.x, v.y, h, l);
    g_xh[i] = h; g_xl[i] = l;
}

__global__ __launch_bounds__(256) void split_wp_kernel(const float* __restrict__ Wp) {
    const int i = blockIdx.x * 256 + threadIdx.x;
    const float2 v = reinterpret_cast<const float2*>(Wp)[i];
    uint32_t h, l;
    split2(v.x, v.y, h, l);
    g_wph[i] = h; g_wpl[i] = l;
}

// W_kqv [h][k][r] -> transposed split rows [j = h*192 + r][k], packed pairs
__global__ __launch_bounds__(256) void wkqv_transpose_split(const float* __restrict__ W) {
    __shared__ float t[32][33];
    const int k0 = blockIdx.x * 32, r0 = blockIdx.y * 32, h = blockIdx.z;
    const float* base = W + (size_t)h * kD * kE;
    const int tid = threadIdx.x;
    #pragma unroll
    for (int it = 0; it < 4; it++) {
        const int idx = tid + it * 256;
        const int kk = idx >> 5, rr = idx & 31;
        t[kk][rr] = base[(size_t)(k0 + kk) * kE + r0 + rr];
    }
    __syncthreads();
    #pragma unroll
    for (int it = 0; it < 2; it++) {
        const int idx = tid + it * 256;
        const int rr = idx >> 4, cc = idx & 15;
        uint32_t hh, ll;
        split2(t[2 * cc][rr], t[2 * cc + 1][rr], hh, ll);
        const int j = h * kE + r0 + rr;
        g_wth[(size_t)j * ROWU + (k0 >> 1) + cc] = hh;
        g_wtl[(size_t)j * ROWU + (k0 >> 1) + cc] = ll;
    }
}

// ===========================================================================
// GEMM core: cp.async double-buffered mainloop over 32-elem K chunks
// ===========================================================================
__device__ __forceinline__ void stage_chunk(uint32_t smb, int buf,
                                            const uint32_t* pAh, const uint32_t* pAl,
                                            const uint32_t* pBh, const uint32_t* pBl,
                                            int tid, int k0u) {
    const uint32_t base = smb + (uint32_t)buf * 4 * TILEU * 4;
    #pragma unroll
    for (int arr = 0; arr < 4; arr++) {
        const uint32_t* s = (arr == 0) ? pAh : (arr == 1) ? pAl : (arr == 2) ? pBh : pBl;
        #pragma unroll
        for (int sub = 0; sub < 2; sub++) {
            const int rem = tid + sub * 256;
            const int row = rem >> 2, part = rem & 3;
            cpa16(base + (uint32_t)((arr * TILEU) + row * LDU + part * 4) * 4,
                  s + (size_t)row * ROWU + k0u + part * 4);
        }
    }
}

__device__ __forceinline__ void chunk_mmas(const uint32_t* __restrict__ sAh,
                                           const uint32_t* __restrict__ sAl,
                                           const uint32_t* __restrict__ sBh,
                                           const uint32_t* __restrict__ sBl,
                                           int wm, int wn, int gid, int tig,
                                           float acc[4][4][4]) {
    #pragma unroll
    for (int ks = 0; ks < 2; ks++) {
        uint32_t bh[4][2], bl[4][2];
        #pragma unroll
        for (int nt = 0; nt < 4; nt++) {
            const int n = wn * 32 + nt * 8 + gid;
            const int base = n * LDU + ks * 8 + tig;
            bh[nt][0] = sBh[base];     bh[nt][1] = sBh[base + 4];
            bl[nt][0] = sBl[base];     bl[nt][1] = sBl[base + 4];
        }
        #pragma unroll
        for (int mt = 0; mt < 4; mt++) {
            const int row = wm * 64 + mt * 16 + gid;
            const int ab = row * LDU + ks * 8 + tig;
            uint32_t ah[4], al[4];
            ah[0] = sAh[ab];       ah[1] = sAh[ab + 8 * LDU];
            ah[2] = sAh[ab + 4];   ah[3] = sAh[ab + 8 * LDU + 4];
            al[0] = sAl[ab];       al[1] = sAl[ab + 8 * LDU];
            al[2] = sAl[ab + 4];   al[3] = sAl[ab + 8 * LDU + 4];
            #pragma unroll
            for (int nt = 0; nt < 4; nt++) {
                mma_bf16(acc[mt][nt], ah, bh[nt]);
                mma_bf16(acc[mt][nt], ah, bl[nt]);
                mma_bf16(acc[mt][nt], al, bh[nt]);
            }
        }
    }
}

__device__ __forceinline__ void gemm_mainloop(const uint32_t* pAh, const uint32_t* pAl,
                                              const uint32_t* pBh, const uint32_t* pBl,
                                              uint32_t* sm, uint32_t smb,
                                              int tid, int wm, int wn, int gid, int tig,
                                              float acc[4][4][4]) {
    stage_chunk(smb, 0, pAh, pAl, pBh, pBl, tid, 0);
    cpa_commit();
    for (int ch = 0; ch < NCH; ch++) {
        const int buf = ch & 1;
        if (ch + 1 < NCH) {
            stage_chunk(smb, buf ^ 1, pAh, pAl, pBh, pBl, tid, (ch + 1) * 16);
            cpa_commit();
            cpa_wait<1>();
        } else {
            cpa_wait<0>();
        }
        __syncthreads();
        const uint32_t* base = sm + (size_t)buf * 4 * TILEU;
        chunk_mmas(base, base + TILEU, base + 2 * TILEU, base + 3 * TILEU,
                   wm, wn, gid, tig, acc);
        __syncthreads();
    }
}

// ---------------------------------------------------------------------------
// Kernel 1: fused KQV projection (reads pre-split x, W^T; writes split q/k/v)
// ---------------------------------------------------------------------------
__global__ __launch_bounds__(256) void kqv_kernel(const float* __restrict__ bias) {
    extern __shared__ uint32_t sm[];
    const uint32_t smb = smem_u32(sm);
    const int tid = threadIdx.x;
    const int wid = tid >> 5, lane = tid & 31;
    const int gid = lane >> 2, tig = lane & 3;
    const int wm = wid & 1, wn = wid >> 1;
    const int m0 = blockIdx.x * 128, n0 = blockIdx.y * 128;

    float acc[4][4][4];
    #pragma unroll
    for (int i = 0; i < 4; i++)
        #pragma unroll
        for (int j = 0; j < 4; j++)
            #pragma unroll
            for (int r = 0; r < 4; r++) acc[i][j][r] = 0.f;

    gemm_mainloop(g_xh + (size_t)m0 * ROWU, g_xl + (size_t)m0 * ROWU,
                  g_wth + (size_t)n0 * ROWU, g_wtl + (size_t)n0 * ROWU,
                  sm, smb, tid, wm, wn, gid, tig, acc);

    #pragma unroll
    for (int nt = 0; nt < 4; nt++) {
        const int j = n0 + wn * 32 + nt * 8 + tig * 2;
        const int h = j / kE, r = j % kE;
        const int chunk = r / kDH, e = r % kDH;
        uint32_t* dh = (chunk == 0) ? g_kh : (chunk == 1 ? g_qh : g_vh);
        uint32_t* dl = (chunk == 0) ? g_kl : (chunk == 1 ? g_ql : g_vl);
        const float b0 = bias[j], b1 = bias[j + 1];
        #pragma unroll
        for (int mt = 0; mt < 4; mt++) {
            #pragma unroll
            for (int h2 = 0; h2 < 2; h2++) {
                const int row_m = m0 + wm * 64 + mt * 16 + gid + h2 * 8;
                const int b_ = row_m >> 11, n = row_m & (kN - 1);
                uint32_t hh, ll;
                split2(acc[mt][nt][h2 * 2 + 0] + b0, acc[mt][nt][h2 * 2 + 1] + b1, hh, ll);
                const size_t di = ((size_t)(b_ * kH + h) * kN + n) * 32 + (e >> 1);
                dh[di] = hh; dl[di] = ll;
            }
        }
    }
}

// ---------------------------------------------------------------------------
// Kernel 3: output projection (reads pre-split sa, W_proj; writes fp32 out)
// ---------------------------------------------------------------------------
__global__ __launch_bounds__(256) void proj_kernel(const float* __restrict__ bp,
                                                   float* __restrict__ out) {
    extern __shared__ uint32_t sm[];
    const uint32_t smb = smem_u32(sm);
    const int tid = threadIdx.x;
    const int wid = tid >> 5, lane = tid & 31;
    const int gid = lane >> 2, tig = lane & 3;
    const int wm = wid & 1, wn = wid >> 1;
    const int m0 = blockIdx.x * 128, n0 = blockIdx.y * 128;

    float acc[4][4][4];
    #pragma unroll
    for (int i = 0; i < 4; i++)
        #pragma unroll
        for (int j = 0; j < 4; j++)
            #pragma unroll
            for (int r = 0; r < 4; r++) acc[i][j][r] = 0.f;

    gemm_mainloop(g_sah + (size_t)m0 * ROWU, g_sal + (size_t)m0 * ROWU,
                  g_wph + (size_t)n0 * ROWU, g_wpl + (size_t)n0 * ROWU,
                  sm, smb, tid, wm, wn, gid, tig, acc);

    #pragma unroll
    for (int nt = 0; nt < 4; nt++) {
        const int n = n0 + wn * 32 + nt * 8 + tig * 2;
        const float b0 = bp[n], b1 = bp[n + 1];
        #pragma unroll
        for (int mt = 0; mt < 4; mt++) {
            #pragma unroll
            for (int h2 = 0; h2 < 2; h2++) {
                const int row_m = m0 + wm * 64 + mt * 16 + gid + h2 * 8;
                float* dst = out + (size_t)row_m * kD + n;
                *reinterpret_cast<float2*>(dst) =
                    make_float2(acc[mt][nt][h2 * 2 + 0] + b0,
                                acc[mt][nt][h2 * 2 + 1] + b1);
            }
        }
    }
}

// ---------------------------------------------------------------------------
// Kernel 2: tensor-core causal flash attention (pre-split inputs/outputs)
// grid (kN/128, kB*kH), 256 threads (8 warps x 16 query rows). Key tiles 64.
// ---------------------------------------------------------------------------
__global__ __launch_bounds__(256, 2) void attn_kernel() {
    __shared__ uint32_t sKh[64 * ALD], sKl[64 * ALD];
    __shared__ uint32_t sVh[64 * ALD], sVl[64 * ALD];   // transposed [dh][key]

    const int qb  = gridDim.x - 1 - blockIdx.x;
    const int bh  = blockIdx.y;
    const int tid = threadIdx.x;
    const int wid = tid >> 5, lane = tid & 31;
    const int gid = lane >> 2, tig = lane & 3;
    const int rb  = qb * 128 + wid * 16;

    const size_t bhbase = (size_t)bh * kN * 32;

    // Q fragments (unscaled; 1/8 applied to S post-MMA — exact)
    uint32_t qh[4][4], ql[4][4];
    {
        const uint32_t* q0h = g_qh + bhbase + (size_t)(rb + gid) * 32;
        const uint32_t* q1h = g_qh + bhbase + (size_t)(rb + gid + 8) * 32;
        const uint32_t* q0l = g_ql + bhbase + (size_t)(rb + gid) * 32;
        const uint32_t* q1l = g_ql + bhbase + (size_t)(rb + gid + 8) * 32;
        #pragma unroll
        for (int ks = 0; ks < 4; ks++) {
            qh[ks][0] = q0h[ks * 8 + tig];     qh[ks][1] = q1h[ks * 8 + tig];
            qh[ks][2] = q0h[ks * 8 + 4 + tig]; qh[ks][3] = q1h[ks * 8 + 4 + tig];
            ql[ks][0] = q0l[ks * 8 + tig];     ql[ks][1] = q1l[ks * 8 + tig];
            ql[ks][2] = q0l[ks * 8 + 4 + tig]; ql[ks][3] = q1l[ks * 8 + 4 + tig];
        }
    }

    float O[8][4];
    #pragma unroll
    for (int i = 0; i < 8; i++)
        #pragma unroll
        for (int c = 0; c < 4; c++) O[i][c] = 0.f;
    float m0 = -1e30f, m1 = -1e30f, l0 = 0.f, l1 = 0.f;

    const int ktiles = 2 * qb + 2;
    const int kd = 2 * qb + (wid >> 2);
    const int skey = tid >> 2, spart = tid & 3;

    for (int kt = 0; kt < ktiles; kt++) {
        __syncthreads();
        {   // stage K rows + V transposed, straight uint copies from pre-split
            const size_t krow = bhbase + (size_t)(kt * 64 + skey) * 32 + spart * 8;
            const uint4 kh0 = *reinterpret_cast<const uint4*>(g_kh + krow);
            const uint4 kh1 = *reinterpret_cast<const uint4*>(g_kh + krow + 4);
            const uint4 kl0 = *reinterpret_cast<const uint4*>(g_kl + krow);
            const uint4 kl1 = *reinterpret_cast<const uint4*>(g_kl + krow + 4);
            uint32_t* dK = &sKh[skey * ALD + spart * 8];
            *reinterpret_cast<uint4*>(dK)     = kh0;
            *reinterpret_cast<uint4*>(dK + 4) = kh1;
            uint32_t* dKl = &sKl[skey * ALD + spart * 8];
            *reinterpret_cast<uint4*>(dKl)     = kl0;
            *reinterpret_cast<uint4*>(dKl + 4) = kl1;

            uint16_t* bVh = reinterpret_cast<uint16_t*>(sVh);
            uint16_t* bVl = reinterpret_cast<uint16_t*>(sVl);
            #pragma unroll
            for (int j = 0; j < 8; j++) {
                const uint32_t vh = g_vh[krow + j];
                const uint32_t vl = g_vl[krow + j];
                const int dh = spart * 16 + 2 * j;
                bVh[dh * (2 * ALD) + skey]       = (uint16_t)(vh & 0xffff);
                bVh[(dh + 1) * (2 * ALD) + skey] = (uint16_t)(vh >> 16);
                bVl[dh * (2 * ALD) + skey]       = (uint16_t)(vl & 0xffff);
                bVl[(dh + 1) * (2 * ALD) + skey] = (uint16_t)(vl >> 16);
            }
        }
        __syncthreads();

        if (kt > kd) continue;

        // S = Q K^T (hh + hl + lh), then scale by 1/8
        float S[8][4];
        #pragma unroll
        for (int i = 0; i < 8; i++)
            #pragma unroll
            for (int c = 0; c < 4; c++) S[i][c] = 0.f;
        #pragma unroll
        for (int nt = 0; nt < 8; nt++) {
            #pragma unroll
            for (int ks = 0; ks < 4; ks++) {
                const int base = (nt * 8 + gid) * ALD + ks * 8 + tig;
                uint32_t bhr[2] = {sKh[base], sKh[base + 4]};
                uint32_t blr[2] = {sKl[base], sKl[base + 4]};
                mma_bf16(S[nt], qh[ks], bhr);
                mma_bf16(S[nt], qh[ks], blr);
                mma_bf16(S[nt], ql[ks], bhr);
            }
        }
        #pragma unroll
        for (int nt = 0; nt < 8; nt++) {
            S[nt][0] *= 0.125f; S[nt][1] *= 0.125f;
            S[nt][2] *= 0.125f; S[nt][3] *= 0.125f;
        }

        if (kt == kd) {
            #pragma unroll
            for (int nt = 0; nt < 8; nt++) {
                #pragma unroll
                for (int c = 0; c < 4; c++) {
                    const int row = rb + gid + (c >> 1) * 8;
                    const int col = kt * 64 + nt * 8 + tig * 2 + (c & 1);
                    if (col > row) S[nt][c] = -1e30f;
                }
            }
        }

        float mx0 = -1e30f, mx1 = -1e30f;
        #pragma unroll
        for (int nt = 0; nt < 8; nt++) {
            mx0 = fmaxf(mx0, fmaxf(S[nt][0], S[nt][1]));
            mx1 = fmaxf(mx1, fmaxf(S[nt][2], S[nt][3]));
        }
        mx0 = fmaxf(mx0, __shfl_xor_sync(0xffffffffu, mx0, 1));
        mx0 = fmaxf(mx0, __shfl_xor_sync(0xffffffffu, mx0, 2));
        mx1 = fmaxf(mx1, __shfl_xor_sync(0xffffffffu, mx1, 1));
        mx1 = fmaxf(mx1, __shfl_xor_sync(0xffffffffu, mx1, 2));

        const float mn0 = fmaxf(m0, mx0), mn1 = fmaxf(m1, mx1);
        const float al0 = __expf(m0 - mn0), al1 = __expf(m1 - mn1);
        m0 = mn0; m1 = mn1;

        float s0 = 0.f, s1 = 0.f;
        #pragma unroll
        for (int nt = 0; nt < 8; nt++) {
            S[nt][0] = __expf(S[nt][0] - mn0); s0 += S[nt][0];
            S[nt][1] = __expf(S[nt][1] - mn0); s0 += S[nt][1];
            S[nt][2] = __expf(S[nt][2] - mn1); s1 += S[nt][2];
            S[nt][3] = __expf(S[nt][3] - mn1); s1 += S[nt][3];
        }
        s0 += __shfl_xor_sync(0xffffffffu, s0, 1);
        s0 += __shfl_xor_sync(0xffffffffu, s0, 2);
        s1 += __shfl_xor_sync(0xffffffffu, s1, 1);
        s1 += __shfl_xor_sync(0xffffffffu, s1, 2);
        l0 = l0 * al0 + s0;
        l1 = l1 * al1 + s1;

        #pragma unroll
        for (int nt = 0; nt < 8; nt++) {
            O[nt][0] *= al0; O[nt][1] *= al0;
            O[nt][2] *= al1; O[nt][3] *= al1;
        }

        #pragma unroll
        for (int ks = 0; ks < 4; ks++) {
            uint32_t ah[4], al_[4];
            split2(S[2 * ks][0],     S[2 * ks][1],     ah[0], al_[0]);
            split2(S[2 * ks][2],     S[2 * ks][3],     ah[1], al_[1]);
            split2(S[2 * ks + 1][0], S[2 * ks + 1][1], ah[2], al_[2]);
            split2(S[2 * ks + 1][2], S[2 * ks + 1][3], ah[3], al_[3]);
            #pragma unroll
            for (int nt = 0; nt < 8; nt++) {
                const int base = (nt * 8 + gid) * ALD + ks * 8 + tig;
                uint32_t bhr[2] = {sVh[base], sVh[base + 4]};
                uint32_t blr[2] = {sVl[base], sVl[base + 4]};
                mma_bf16(O[nt], ah, bhr);
                mma_bf16(O[nt], ah, blr);
                mma_bf16(O[nt], al_, bhr);
            }
        }
    }

    // epilogue: normalize, split, write packed hi/lo sa rows
    const float inv0 = 1.f / l0, inv1 = 1.f / l1;
    const int b_ = bh / kH, h = bh % kH;
    uint32_t* oh0 = g_sah + ((size_t)(b_ * kN) + rb + gid) * ROWU + h * 32;
    uint32_t* ol0 = g_sal + ((size_t)(b_ * kN) + rb + gid) * ROWU + h * 32;
    uint32_t* oh1 = g_sah + ((size_t)(b_ * kN) + rb + gid + 8) * ROWU + h * 32;
    uint32_t* ol1 = g_sal + ((size_t)(b_ * kN) + rb + gid + 8) * ROWU + h * 32;
    #pragma unroll
    for (int nt = 0; nt < 8; nt++) {
        uint32_t hh, ll;
        split2(O[nt][0] * inv0, O[nt][1] * inv0, hh, ll);
        oh0[nt * 4 + tig] = hh; ol0[nt * 4 + tig] = ll;
        split2(O[nt][2] * inv1, O[nt][3] * inv1, hh, ll);
        oh1[nt * 4 + tig] = hh; ol1[nt * 4 + tig] = ll;
    }
}

// ---------------------------------------------------------------------------
extern "C" void kernel_launch(void* const* d_in, const int* in_sizes, int n_in,
                              void* d_out, int out_size) {
    (void)in_sizes; (void)n_in; (void)out_size;
    const float* x      = (const float*)d_in[0];
    const float* W_kqv  = (const float*)d_in[1];
    const float* b_kqv  = (const float*)d_in[2];
    const float* W_proj = (const float*)d_in[3];
    const float* b_proj = (const float*)d_in[4];
    float* out = (float*)d_out;

    // idempotent, deterministic attribute setup (not a stream op)
    cudaFuncSetAttribute(kqv_kernel, cudaFuncAttributeMaxDynamicSharedMemorySize, GEMM_SMEM);
    cudaFuncSetAttribute(proj_kernel, cudaFuncAttributeMaxDynamicSharedMemorySize, GEMM_SMEM);

    split_x_kernel<<<(kM * ROWU) / 256, 256>>>(x);
    split_wp_kernel<<<(kD * ROWU) / 256, 256>>>(W_proj);
    wkqv_transpose_split<<<dim3(kD / 32, kE / 32, kH), 256>>>(W_kqv);

    dim3 gA(kM / 128, kEtot / 128);
    kqv_kernel<<<gA, 256, GEMM_SMEM>>>(b_kqv);

    dim3 gB(kN / 128, kB * kH);
    attn_kernel<<<gB, 256>>>();

    dim3 gC(kM / 128, kD / 128);
    proj_kernel<<<gC, 256, GEMM_SMEM>>>(b_proj, out);
}

// round 17
// speedup vs baseline: 4.5091x; 1.1816x over previous
#include <cuda_runtime.h>
#include <cuda_bf16.h>
#include <cstdint>
#include <cstddef>

// Problem constants
namespace {
constexpr int kB  = 2;
constexpr int kN  = 2048;
constexpr int kD  = 1024;
constexpr int kH  = 16;
constexpr int kDH = 64;
constexpr int kM  = kB * kN;         // 4096
constexpr int kE  = 3 * kDH;         // 192
constexpr int kEtot = kH * kE;       // 3072

constexpr int LDU  = 20;             // GEMM smem row stride (uints), ldmatrix conflict-free
constexpr int ALD  = 36;             // attention smem row stride (uints), ldmatrix conflict-free
constexpr int ROWU = kD / 2;         // 512 packed uints per 1024-elem row
constexpr int TILEU = 128 * LDU;     // 2560 uints per tile array
constexpr int GEMM_SMEM = 2 * 4 * TILEU * 4;   // 81920 B dynamic smem
constexpr int NCH = kD / 32;         // 32 K-chunks of 32

constexpr int ATILE = 64 * ALD;      // 2304 uints per attention tile array
constexpr int ATOT  = 4 * ATILE;     // Kh,Kl,Vh,Vl per buffer
constexpr int ATT_SMEM = 2 * ATOT * 4;  // 73728 B dynamic smem (double buffered)
}

// ---------------------------------------------------------------------------
// Pre-split packed bf16 hi/lo pair buffers (device globals; no runtime alloc)
// ---------------------------------------------------------------------------
__device__ uint32_t g_xh[kM * ROWU],    g_xl[kM * ROWU];       // x rows
__device__ uint32_t g_wth[kEtot * ROWU], g_wtl[kEtot * ROWU];  // W_kqv^T rows [j][k]
__device__ uint32_t g_wph[kD * ROWU],   g_wpl[kD * ROWU];      // W_proj rows [n][k]
__device__ uint32_t g_qh[kB * kH * kN * 32], g_ql[kB * kH * kN * 32];
__device__ uint32_t g_kh[kB * kH * kN * 32], g_kl[kB * kH * kN * 32];
__device__ uint32_t g_vh[kB * kH * kN * 32], g_vl[kB * kH * kN * 32];
__device__ uint32_t g_sah[kM * ROWU],   g_sal[kM * ROWU];      // attention out rows

// ===========================================================================
// Helpers
// ===========================================================================
__device__ __forceinline__ void mma_bf16(float* d, const uint32_t* a, const uint32_t* b) {
    asm volatile(
        "mma.sync.aligned.m16n8k16.row.col.f32.bf16.bf16.f32 "
        "{%0,%1,%2,%3}, {%4,%5,%6,%7}, {%8,%9}, {%0,%1,%2,%3};"
        : "+f"(d[0]), "+f"(d[1]), "+f"(d[2]), "+f"(d[3])
        : "r"(a[0]), "r"(a[1]), "r"(a[2]), "r"(a[3]), "r"(b[0]), "r"(b[1]));
}

__device__ __forceinline__ void ldm4(uint32_t* r, uint32_t a) {
    asm volatile("ldmatrix.sync.aligned.m8n8.x4.shared.b16 {%0,%1,%2,%3}, [%4];"
                 : "=r"(r[0]), "=r"(r[1]), "=r"(r[2]), "=r"(r[3]) : "r"(a));
}
__device__ __forceinline__ void ldm4t(uint32_t* r, uint32_t a) {
    asm volatile("ldmatrix.sync.aligned.m8n8.x4.trans.shared.b16 {%0,%1,%2,%3}, [%4];"
                 : "=r"(r[0]), "=r"(r[1]), "=r"(r[2]), "=r"(r[3]) : "r"(a));
}

__device__ __forceinline__ void split2(float a, float b, uint32_t& hi, uint32_t& lo) {
    __nv_bfloat16 ha = __float2bfloat16(a), hb = __float2bfloat16(b);
    float ra = a - __bfloat162float(ha);
    float rb = b - __bfloat162float(hb);
    __nv_bfloat16 la = __float2bfloat16(ra), lb = __float2bfloat16(rb);
    hi = (uint32_t)__bfloat16_as_ushort(ha) | ((uint32_t)__bfloat16_as_ushort(hb) << 16);
    lo = (uint32_t)__bfloat16_as_ushort(la) | ((uint32_t)__bfloat16_as_ushort(lb) << 16);
}

__device__ __forceinline__ uint32_t smem_u32(const void* p) {
    uint32_t a;
    asm("{ .reg .u64 t; cvta.to.shared.u64 t, %1; cvt.u32.u64 %0, t; }" : "=r"(a) : "l"(p));
    return a;
}
__device__ __forceinline__ void cpa16(uint32_t dst, const uint32_t* src) {
    asm volatile("cp.async.cg.shared.global [%0], [%1], 16;" :: "r"(dst), "l"(src));
}
__device__ __forceinline__ void cpa_commit() {
    asm volatile("cp.async.commit_group;" ::: "memory");
}
template <int N>
__device__ __forceinline__ void cpa_wait() {
    asm volatile("cp.async.wait_group %0;" :: "n"(N) : "memory");
}

// ===========================================================================
// Pre-split kernels
// ===========================================================================
__global__ __launch_bounds__(256) void split_x_kernel(const float* __restrict__ x) {
    const int i = blockIdx.x * 256 + threadIdx.x;          // pair index
    const float2 v = reinterpret_cast<const float2*>(x)[i];
    uint32_t h, l;
    split2(v.x, v.y, h, l);
    g_xh[i] = h; g_xl[i] = l;
}

__global__ __launch_bounds__(256) void split_wp_kernel(const float* __restrict__ Wp) {
    const int i = blockIdx.x * 256 + threadIdx.x;
    const float2 v = reinterpret_cast<const float2*>(Wp)[i];
    uint32_t h, l;
    split2(v.x, v.y, h, l);
    g_wph[i] = h; g_wpl[i] = l;
}

// W_kqv [h][k][r] -> transposed split rows [j = h*192 + r][k], packed pairs
__global__ __launch_bounds__(256) void wkqv_transpose_split(const float* __restrict__ W) {
    __shared__ float t[32][33];
    const int k0 = blockIdx.x * 32, r0 = blockIdx.y * 32, h = blockIdx.z;
    const float* base = W + (size_t)h * kD * kE;
    const int tid = threadIdx.x;
    #pragma unroll
    for (int it = 0; it < 4; it++) {
        const int idx = tid + it * 256;
        const int kk = idx >> 5, rr = idx & 31;
        t[kk][rr] = base[(size_t)(k0 + kk) * kE + r0 + rr];
    }
    __syncthreads();
    #pragma unroll
    for (int it = 0; it < 2; it++) {
        const int idx = tid + it * 256;
        const int rr = idx >> 4, cc = idx & 15;
        uint32_t hh, ll;
        split2(t[2 * cc][rr], t[2 * cc + 1][rr], hh, ll);
        const int j = h * kE + r0 + rr;
        g_wth[(size_t)j * ROWU + (k0 >> 1) + cc] = hh;
        g_wtl[(size_t)j * ROWU + (k0 >> 1) + cc] = ll;
    }
}

// ===========================================================================
// GEMM core: cp.async pipelined mainloop (single sync/chunk) + ldmatrix frags
// ===========================================================================
__device__ __forceinline__ void stage_chunk(uint32_t smb, int buf,
                                            const uint32_t* pAh, const uint32_t* pAl,
                                            const uint32_t* pBh, const uint32_t* pBl,
                                            int tid, int k0u) {
    const uint32_t base = smb + (uint32_t)buf * 4 * TILEU * 4;
    #pragma unroll
    for (int arr = 0; arr < 4; arr++) {
        const uint32_t* s = (arr == 0) ? pAh : (arr == 1) ? pAl : (arr == 2) ? pBh : pBl;
        #pragma unroll
        for (int sub = 0; sub < 2; sub++) {
            const int rem = tid + sub * 256;
            const int row = rem >> 2, part = rem & 3;
            cpa16(base + (uint32_t)((arr * TILEU) + row * LDU + part * 4) * 4,
                  s + (size_t)row * ROWU + k0u + part * 4);
        }
    }
}

// sA/sB = smem u32 addrs of hi tiles; lo tiles at +TILEU*4 bytes
__device__ __forceinline__ void chunk_mmas(uint32_t sA, uint32_t sB,
                                           int wm, int wn, int lane,
                                           float acc[4][4][4]) {
    const int mi = lane >> 3, li = lane & 7;
    const uint32_t aoff = (uint32_t)((wm * 64 + (mi & 1) * 8 + li) * LDU * 4 + (mi >> 1) * 16);
    const uint32_t boff = (uint32_t)((wn * 32 + (mi >> 1) * 8 + li) * LDU * 4 + (mi & 1) * 16);
    #pragma unroll
    for (int ks = 0; ks < 2; ks++) {
        uint32_t Bh[2][4], Bl[2][4];
        #pragma unroll
        for (int ntp = 0; ntp < 2; ntp++) {
            const uint32_t ab = sB + boff + (uint32_t)(ntp * 16 * LDU * 4 + ks * 32);
            ldm4(Bh[ntp], ab);
            ldm4(Bl[ntp], ab + TILEU * 4);
        }
        #pragma unroll
        for (int mt = 0; mt < 4; mt++) {
            const uint32_t aa = sA + aoff + (uint32_t)(mt * 16 * LDU * 4 + ks * 32);
            uint32_t Ah[4], Al[4];
            ldm4(Ah, aa);
            ldm4(Al, aa + TILEU * 4);
            #pragma unroll
            for (int nt = 0; nt < 4; nt++) {
                const uint32_t* bh = &Bh[nt >> 1][(nt & 1) * 2];
                const uint32_t* bl = &Bl[nt >> 1][(nt & 1) * 2];
                mma_bf16(acc[mt][nt], Ah, bh);
                mma_bf16(acc[mt][nt], Ah, bl);
                mma_bf16(acc[mt][nt], Al, bh);
            }
        }
    }
}

__device__ __forceinline__ void gemm_mainloop(const uint32_t* pAh, const uint32_t* pAl,
                                              const uint32_t* pBh, const uint32_t* pBl,
                                              uint32_t smb, int tid, int wm, int wn,
                                              int lane, float acc[4][4][4]) {
    stage_chunk(smb, 0, pAh, pAl, pBh, pBl, tid, 0);
    cpa_commit();
    for (int ch = 0; ch < NCH; ch++) {
        const int buf = ch & 1;
        cpa_wait<0>();
        __syncthreads();
        if (ch + 1 < NCH) {
            stage_chunk(smb, buf ^ 1, pAh, pAl, pBh, pBl, tid, (ch + 1) * 16);
            cpa_commit();
        }
        const uint32_t base = smb + (uint32_t)buf * 4 * TILEU * 4;
        chunk_mmas(base, base + 2 * TILEU * 4, wm, wn, lane, acc);
    }
}

// ---------------------------------------------------------------------------
// Kernel 1: fused KQV projection (reads pre-split x, W^T; writes split q/k/v)
// ---------------------------------------------------------------------------
__global__ __launch_bounds__(256) void kqv_kernel(const float* __restrict__ bias) {
    extern __shared__ uint32_t sm[];
    const uint32_t smb = smem_u32(sm);
    const int tid = threadIdx.x;
    const int wid = tid >> 5, lane = tid & 31;
    const int gid = lane >> 2, tig = lane & 3;
    const int wm = wid & 1, wn = wid >> 1;
    const int m0 = blockIdx.x * 128, n0 = blockIdx.y * 128;

    float acc[4][4][4];
    #pragma unroll
    for (int i = 0; i < 4; i++)
        #pragma unroll
        for (int j = 0; j < 4; j++)
            #pragma unroll
            for (int r = 0; r < 4; r++) acc[i][j][r] = 0.f;

    gemm_mainloop(g_xh + (size_t)m0 * ROWU, g_xl + (size_t)m0 * ROWU,
                  g_wth + (size_t)n0 * ROWU, g_wtl + (size_t)n0 * ROWU,
                  smb, tid, wm, wn, lane, acc);

    #pragma unroll
    for (int nt = 0; nt < 4; nt++) {
        const int j = n0 + wn * 32 + nt * 8 + tig * 2;
        const int h = j / kE, r = j % kE;
        const int chunk = r / kDH, e = r % kDH;
        uint32_t* dh = (chunk == 0) ? g_kh : (chunk == 1 ? g_qh : g_vh);
        uint32_t* dl = (chunk == 0) ? g_kl : (chunk == 1 ? g_ql : g_vl);
        const float b0 = bias[j], b1 = bias[j + 1];
        #pragma unroll
        for (int mt = 0; mt < 4; mt++) {
            #pragma unroll
            for (int h2 = 0; h2 < 2; h2++) {
                const int row_m = m0 + wm * 64 + mt * 16 + gid + h2 * 8;
                const int b_ = row_m >> 11, n = row_m & (kN - 1);
                uint32_t hh, ll;
                split2(acc[mt][nt][h2 * 2 + 0] + b0, acc[mt][nt][h2 * 2 + 1] + b1, hh, ll);
                const size_t di = ((size_t)(b_ * kH + h) * kN + n) * 32 + (e >> 1);
                dh[di] = hh; dl[di] = ll;
            }
        }
    }
}

// ---------------------------------------------------------------------------
// Kernel 3: output projection (reads pre-split sa, W_proj; writes fp32 out)
// ---------------------------------------------------------------------------
__global__ __launch_bounds__(256) void proj_kernel(const float* __restrict__ bp,
                                                   float* __restrict__ out) {
    extern __shared__ uint32_t sm[];
    const uint32_t smb = smem_u32(sm);
    const int tid = threadIdx.x;
    const int wid = tid >> 5, lane = tid & 31;
    const int gid = lane >> 2, tig = lane & 3;
    const int wm = wid & 1, wn = wid >> 1;
    const int m0 = blockIdx.x * 128, n0 = blockIdx.y * 128;

    float acc[4][4][4];
    #pragma unroll
    for (int i = 0; i < 4; i++)
        #pragma unroll
        for (int j = 0; j < 4; j++)
            #pragma unroll
            for (int r = 0; r < 4; r++) acc[i][j][r] = 0.f;

    gemm_mainloop(g_sah + (size_t)m0 * ROWU, g_sal + (size_t)m0 * ROWU,
                  g_wph + (size_t)n0 * ROWU, g_wpl + (size_t)n0 * ROWU,
                  smb, tid, wm, wn, lane, acc);

    #pragma unroll
    for (int nt = 0; nt < 4; nt++) {
        const int n = n0 + wn * 32 + nt * 8 + tig * 2;
        const float b0 = bp[n], b1 = bp[n + 1];
        #pragma unroll
        for (int mt = 0; mt < 4; mt++) {
            #pragma unroll
            for (int h2 = 0; h2 < 2; h2++) {
                const int row_m = m0 + wm * 64 + mt * 16 + gid + h2 * 8;
                float* dst = out + (size_t)row_m * kD + n;
                *reinterpret_cast<float2*>(dst) =
                    make_float2(acc[mt][nt][h2 * 2 + 0] + b0,
                                acc[mt][nt][h2 * 2 + 1] + b1);
            }
        }
    }
}

// ---------------------------------------------------------------------------
// Kernel 2: tensor-core causal flash attention.
// V kept in [key][dh] layout (staged identically to K via cp.async);
// PV B-fragments via ldmatrix.trans. Double-buffered K/V tiles, single sync.
// grid (kN/128, kB*kH), 256 threads (8 warps x 16 query rows). Key tiles 64.
// ---------------------------------------------------------------------------
__device__ __forceinline__ void stage_att(uint32_t smb, int buf, size_t bhbase,
                                          int kt, int tid) {
    #pragma unroll
    for (int i = 0; i < 8; i++) {
        const int gi = tid + i * 256;
        const int arr = gi >> 9, rem = gi & 511;
        const int row = rem >> 3, part = rem & 7;
        const uint32_t* src = (arr == 0) ? g_kh : (arr == 1) ? g_kl
                            : (arr == 2) ? g_vh : g_vl;
        cpa16(smb + (uint32_t)(buf * ATOT + arr * ATILE + row * ALD) * 4 + part * 16,
              src + bhbase + (size_t)(kt * 64 + row) * 32 + part * 4);
    }
}

__global__ __launch_bounds__(256, 2) void attn_kernel() {
    extern __shared__ uint32_t sm[];
    const uint32_t smb = smem_u32(sm);

    const int qb  = gridDim.x - 1 - blockIdx.x;
    const int bh  = blockIdx.y;
    const int tid = threadIdx.x;
    const int wid = tid >> 5, lane = tid & 31;
    const int gid = lane >> 2, tig = lane & 3;
    const int mi = lane >> 3, li = lane & 7;
    const int rb  = qb * 128 + wid * 16;

    const size_t bhbase = (size_t)bh * kN * 32;

    // ldmatrix per-thread offsets
    const uint32_t kfoff = (uint32_t)(((mi >> 1) * 8 + li) * ALD * 4 + (mi & 1) * 16);
    const uint32_t vfoff = (uint32_t)(((mi & 1) * 8 + li) * ALD * 4 + (mi >> 1) * 16);

    // Q fragments (unscaled; 1/8 applied to S post-MMA — exact)
    uint32_t qh[4][4], ql[4][4];
    {
        const uint32_t* q0h = g_qh + bhbase + (size_t)(rb + gid) * 32;
        const uint32_t* q1h = g_qh + bhbase + (size_t)(rb + gid + 8) * 32;
        const uint32_t* q0l = g_ql + bhbase + (size_t)(rb + gid) * 32;
        const uint32_t* q1l = g_ql + bhbase + (size_t)(rb + gid + 8) * 32;
        #pragma unroll
        for (int ks = 0; ks < 4; ks++) {
            qh[ks][0] = q0h[ks * 8 + tig];     qh[ks][1] = q1h[ks * 8 + tig];
            qh[ks][2] = q0h[ks * 8 + 4 + tig]; qh[ks][3] = q1h[ks * 8 + 4 + tig];
            ql[ks][0] = q0l[ks * 8 + tig];     ql[ks][1] = q1l[ks * 8 + tig];
            ql[ks][2] = q0l[ks * 8 + 4 + tig]; ql[ks][3] = q1l[ks * 8 + 4 + tig];
        }
    }

    float O[8][4];
    #pragma unroll
    for (int i = 0; i < 8; i++)
        #pragma unroll
        for (int c = 0; c < 4; c++) O[i][c] = 0.f;
    float m0 = -1e30f, m1 = -1e30f, l0 = 0.f, l1 = 0.f;

    const int ktiles = 2 * qb + 2;
    const int kd = 2 * qb + (wid >> 2);

    stage_att(smb, 0, bhbase, 0, tid);
    cpa_commit();

    for (int kt = 0; kt < ktiles; kt++) {
        const int buf = kt & 1;
        cpa_wait<0>();
        __syncthreads();
        if (kt + 1 < ktiles) {
            stage_att(smb, buf ^ 1, bhbase, kt + 1, tid);
            cpa_commit();
        }

        if (kt > kd) continue;

        const uint32_t sK = smb + (uint32_t)(buf * ATOT) * 4;               // Kh; Kl +ATILE*4
        const uint32_t sV = smb + (uint32_t)(buf * ATOT + 2 * ATILE) * 4;   // Vh; Vl +ATILE*4

        // --- S = Q K^T (hh + hl + lh) ---
        float S[8][4];
        #pragma unroll
        for (int i = 0; i < 8; i++)
            #pragma unroll
            for (int c = 0; c < 4; c++) S[i][c] = 0.f;
        #pragma unroll
        for (int ks = 0; ks < 4; ks++) {
            #pragma unroll
            for (int ntp = 0; ntp < 4; ntp++) {
                const uint32_t a = sK + kfoff + (uint32_t)(ntp * 16 * ALD * 4 + ks * 32);
                uint32_t Bh[4], Bl[4];
                ldm4(Bh, a);
                ldm4(Bl, a + ATILE * 4);
                #pragma unroll
                for (int hf = 0; hf < 2; hf++) {
                    const int nt = 2 * ntp + hf;
                    mma_bf16(S[nt], qh[ks], &Bh[hf * 2]);
                    mma_bf16(S[nt], qh[ks], &Bl[hf * 2]);
                    mma_bf16(S[nt], ql[ks], &Bh[hf * 2]);
                }
            }
        }
        #pragma unroll
        for (int nt = 0; nt < 8; nt++) {
            S[nt][0] *= 0.125f; S[nt][1] *= 0.125f;
            S[nt][2] *= 0.125f; S[nt][3] *= 0.125f;
        }

        if (kt == kd) {
            #pragma unroll
            for (int nt = 0; nt < 8; nt++) {
                #pragma unroll
                for (int c = 0; c < 4; c++) {
                    const int row = rb + gid + (c >> 1) * 8;
                    const int col = kt * 64 + nt * 8 + tig * 2 + (c & 1);
                    if (col > row) S[nt][c] = -1e30f;
                }
            }
        }

        float mx0 = -1e30f, mx1 = -1e30f;
        #pragma unroll
        for (int nt = 0; nt < 8; nt++) {
            mx0 = fmaxf(mx0, fmaxf(S[nt][0], S[nt][1]));
            mx1 = fmaxf(mx1, fmaxf(S[nt][2], S[nt][3]));
        }
        mx0 = fmaxf(mx0, __shfl_xor_sync(0xffffffffu, mx0, 1));
        mx0 = fmaxf(mx0, __shfl_xor_sync(0xffffffffu, mx0, 2));
        mx1 = fmaxf(mx1, __shfl_xor_sync(0xffffffffu, mx1, 1));
        mx1 = fmaxf(mx1, __shfl_xor_sync(0xffffffffu, mx1, 2));

        const float mn0 = fmaxf(m0, mx0), mn1 = fmaxf(m1, mx1);
        const float al0 = __expf(m0 - mn0), al1 = __expf(m1 - mn1);
        m0 = mn0; m1 = mn1;

        float s0 = 0.f, s1 = 0.f;
        #pragma unroll
        for (int nt = 0; nt < 8; nt++) {
            S[nt][0] = __expf(S[nt][0] - mn0); s0 += S[nt][0];
            S[nt][1] = __expf(S[nt][1] - mn0); s0 += S[nt][1];
            S[nt][2] = __expf(S[nt][2] - mn1); s1 += S[nt][2];
            S[nt][3] = __expf(S[nt][3] - mn1); s1 += S[nt][3];
        }
        s0 += __shfl_xor_sync(0xffffffffu, s0, 1);
        s0 += __shfl_xor_sync(0xffffffffu, s0, 2);
        s1 += __shfl_xor_sync(0xffffffffu, s1, 1);
        s1 += __shfl_xor_sync(0xffffffffu, s1, 2);
        l0 = l0 * al0 + s0;
        l1 = l1 * al1 + s1;

        #pragma unroll
        for (int nt = 0; nt < 8; nt++) {
            O[nt][0] *= al0; O[nt][1] *= al0;
            O[nt][2] *= al1; O[nt][3] *= al1;
        }

        // --- O += P V, V via ldmatrix.trans of [key][dh] tile ---
        #pragma unroll
        for (int ks = 0; ks < 4; ks++) {
            uint32_t ah[4], al_[4];
            split2(S[2 * ks][0],     S[2 * ks][1],     ah[0], al_[0]);
            split2(S[2 * ks][2],     S[2 * ks][3],     ah[1], al_[1]);
            split2(S[2 * ks + 1][0], S[2 * ks + 1][1], ah[2], al_[2]);
            split2(S[2 * ks + 1][2], S[2 * ks + 1][3], ah[3], al_[3]);
            #pragma unroll
            for (int ntp = 0; ntp < 4; ntp++) {
                const uint32_t a = sV + vfoff + (uint32_t)(ks * 16 * ALD * 4 + ntp * 32);
                uint32_t Bh[4], Bl[4];
                ldm4t(Bh, a);
                ldm4t(Bl, a + ATILE * 4);
                #pragma unroll
                for (int hf = 0; hf < 2; hf++) {
                    const int nt = 2 * ntp + hf;
                    mma_bf16(O[nt], ah, &Bh[hf * 2]);
                    mma_bf16(O[nt], ah, &Bl[hf * 2]);
                    mma_bf16(O[nt], al_, &Bh[hf * 2]);
                }
            }
        }
    }

    // epilogue: normalize, split, write packed hi/lo sa rows
    const float inv0 = 1.f / l0, inv1 = 1.f / l1;
    const int b_ = bh / kH, h = bh % kH;
    uint32_t* oh0 = g_sah + ((size_t)(b_ * kN) + rb + gid) * ROWU + h * 32;
    uint32_t* ol0 = g_sal + ((size_t)(b_ * kN) + rb + gid) * ROWU + h * 32;
    uint32_t* oh1 = g_sah + ((size_t)(b_ * kN) + rb + gid + 8) * ROWU + h * 32;
    uint32_t* ol1 = g_sal + ((size_t)(b_ * kN) + rb + gid + 8) * ROWU + h * 32;
    #pragma unroll
    for (int nt = 0; nt < 8; nt++) {
        uint32_t hh, ll;
        split2(O[nt][0] * inv0, O[nt][1] * inv0, hh, ll);
        oh0[nt * 4 + tig] = hh; ol0[nt * 4 + tig] = ll;
        split2(O[nt][2] * inv1, O[nt][3] * inv1, hh, ll);
        oh1[nt * 4 + tig] = hh; ol1[nt * 4 + tig] = ll;
    }
}

// ---------------------------------------------------------------------------
extern "C" void kernel_launch(void* const* d_in, const int* in_sizes, int n_in,
                              void* d_out, int out_size) {
    (void)in_sizes; (void)n_in; (void)out_size;
    const float* x      = (const float*)d_in[0];
    const float* W_kqv  = (const float*)d_in[1];
    const float* b_kqv  = (const float*)d_in[2];
    const float* W_proj = (const float*)d_in[3];
    const float* b_proj = (const float*)d_in[4];
    float* out = (float*)d_out;

    // idempotent, deterministic attribute setup (not a stream op)
    cudaFuncSetAttribute(kqv_kernel, cudaFuncAttributeMaxDynamicSharedMemorySize, GEMM_SMEM);
    cudaFuncSetAttribute(proj_kernel, cudaFuncAttributeMaxDynamicSharedMemorySize, GEMM_SMEM);
    cudaFuncSetAttribute(attn_kernel, cudaFuncAttributeMaxDynamicSharedMemorySize, ATT_SMEM);

    split_x_kernel<<<(kM * ROWU) / 256, 256>>>(x);
    split_wp_kernel<<<(kD * ROWU) / 256, 256>>>(W_proj);
    wkqv_transpose_split<<<dim3(kD / 32, kE / 32, kH), 256>>>(W_kqv);

    dim3 gA(kM / 128, kEtot / 128);
    kqv_kernel<<<gA, 256, GEMM_SMEM>>>(b_kqv);

    dim3 gB(kN / 128, kB * kH);
    attn_kernel<<<gB, 256, ATT_SMEM>>>();

    dim3 gC(kM / 128, kD / 128);
    proj_kernel<<<gC, 256, GEMM_SMEM>>>(b_proj, out);
}